// round 2
// baseline (speedup 1.0000x reference)
#include <cuda_runtime.h>
#include <cuda_bf16.h>
#include <cfloat>
#include <cstdint>

// Problem constants
#define BB_   64
#define NN_   512
#define DIM_  256
#define HH_   8
#define DHH_  64
#define INNER_ 512
#define SCALE_ 0.125f   // 64^-0.5

// Scratch (device globals; no allocation allowed)
__device__ float g_Q[BB_*HH_*NN_*DHH_];   // [b,h,n,d]
__device__ float g_K[BB_*HH_*NN_*DHH_];
__device__ float g_V[BB_*HH_*NN_*DHH_];
__device__ float g_G[BB_*NN_*INNER_];     // gates [m, inner]
__device__ float g_AO[BB_*NN_*INNER_];    // attention out, b n (h d)
__device__ unsigned char g_mask[BB_*NN_]; // canonical 0/1 mask
__device__ int g_mask_mode;               // 0=int32, 1=float32, 2=uint8

// ---------------------------------------------------------------------------
// Mask dtype detection: scan first 8192 words (valid under every candidate
// dtype: int32 buffer has 32768 words, float32 32768, uint8 8192).
// ---------------------------------------------------------------------------
__global__ void detect_mask_kernel(const unsigned int* __restrict__ m)
{
  __shared__ int s_not01, s_notf;
  if (threadIdx.x == 0) { s_not01 = 0; s_notf = 0; }
  __syncthreads();
  int a = 0, b = 0;
  for (int i = threadIdx.x; i < 8192; i += 256) {
    unsigned v = m[i];
    if (v != 0u && v != 1u) a = 1;
    if (v != 0u && v != 0x3F800000u) b = 1;
  }
  if (a) atomicOr(&s_not01, 1);
  if (b) atomicOr(&s_notf, 1);
  __syncthreads();
  if (threadIdx.x == 0)
    g_mask_mode = (!s_not01) ? 0 : ((!s_notf) ? 1 : 2);
}

__global__ void convert_mask_kernel(const void* __restrict__ m)
{
  int idx = blockIdx.x * blockDim.x + threadIdx.x;
  if (idx >= BB_*NN_) return;
  int mode = g_mask_mode;
  unsigned char r;
  if (mode == 0)      r = ((const int*)m)[idx] != 0;
  else if (mode == 1) r = ((const unsigned int*)m)[idx] != 0u; // 0x3F800000 or 0
  else                r = ((const unsigned char*)m)[idx] != 0;
  g_mask[idx] = r;
}

// ---------------------------------------------------------------------------
// Kernel 1: fused projection GEMM.
// A = x [M=32768, K=256]; virtual B [256, 2048] = [Wq | Wkv(k) | Wkv(v) | Wg]
// Scatters outputs into g_Q/g_K/g_V ([b,h,n,d]) and g_G (+bg).
// ---------------------------------------------------------------------------
__global__ __launch_bounds__(256, 2) void proj_kernel(
    const float* __restrict__ x, const float* __restrict__ Wq,
    const float* __restrict__ Wkv, const float* __restrict__ Wg,
    const float* __restrict__ bg)
{
  __shared__ float As[8*132];
  __shared__ float Bs[8*128];
  const int tid = threadIdx.x;
  const int c0 = blockIdx.x * 128;
  const int m0 = blockIdx.y * 128;

  const float* Bp; int ldb, cb, seg;
  if (c0 < 512)       { Bp = Wq;  ldb = 512;  cb = c0;        seg = 0; }
  else if (c0 < 1536) { Bp = Wkv; ldb = 1024; cb = c0 - 512;  seg = (c0 < 1024) ? 1 : 2; }
  else                { Bp = Wg;  ldb = 512;  cb = c0 - 1536; seg = 3; }

  const int arow = tid >> 1, acol = (tid & 1) * 4;
  const int brow = tid >> 5, bcol = (tid & 31) * 4;
  const int tx = tid & 15, ty = tid >> 4;

  float acc[8][8];
#pragma unroll
  for (int i = 0; i < 8; i++)
#pragma unroll
    for (int j = 0; j < 8; j++) acc[i][j] = 0.f;

  const float* aptr = x + (m0 + arow) * 256 + acol;
  const float* bptr = Bp + brow * ldb + cb + bcol;

  for (int kk = 0; kk < 256; kk += 8) {
    float4 av = *(const float4*)(aptr + kk);
    As[(acol+0)*132 + arow] = av.x;
    As[(acol+1)*132 + arow] = av.y;
    As[(acol+2)*132 + arow] = av.z;
    As[(acol+3)*132 + arow] = av.w;
    *(float4*)&Bs[brow*128 + bcol] = *(const float4*)(bptr + kk * ldb);
    __syncthreads();
#pragma unroll
    for (int k = 0; k < 8; k++) {
      float4 a0 = *(float4*)&As[k*132 + ty*4];
      float4 a1 = *(float4*)&As[k*132 + 64 + ty*4];
      float4 b0 = *(float4*)&Bs[k*128 + tx*4];
      float4 b1 = *(float4*)&Bs[k*128 + 64 + tx*4];
      float a[8] = {a0.x,a0.y,a0.z,a0.w,a1.x,a1.y,a1.z,a1.w};
      float b[8] = {b0.x,b0.y,b0.z,b0.w,b1.x,b1.y,b1.z,b1.w};
#pragma unroll
      for (int i = 0; i < 8; i++)
#pragma unroll
        for (int j = 0; j < 8; j++) acc[i][j] += a[i]*b[j];
    }
    __syncthreads();
  }

  float4 bg0 = make_float4(0,0,0,0), bg1 = make_float4(0,0,0,0);
  if (seg == 3) {
    bg0 = *(const float4*)(bg + c0 - 1536 + tx*4);
    bg1 = *(const float4*)(bg + c0 - 1536 + 64 + tx*4);
  }
#pragma unroll
  for (int i = 0; i < 8; i++) {
    int r = (i < 4) ? (ty*4 + i) : (64 + ty*4 + (i - 4));
    int m = m0 + r;
    int bidx = m >> 9, n = m & 511;
#pragma unroll
    for (int g = 0; g < 2; g++) {
      int cg = c0 + g*64 + tx*4;
      float4 v;
      v.x = acc[i][g*4+0]; v.y = acc[i][g*4+1];
      v.z = acc[i][g*4+2]; v.w = acc[i][g*4+3];
      if (seg == 3) {
        float4 bv = g ? bg1 : bg0;
        v.x += bv.x; v.y += bv.y; v.z += bv.z; v.w += bv.w;
        *(float4*)(g_G + m*512 + (cg - 1536)) = v;
      } else {
        int local = cg - seg*512;
        int hh = local >> 6, dd = local & 63;
        float* base = (seg == 0) ? g_Q : ((seg == 1) ? g_K : g_V);
        *(float4*)(base + (((bidx*8 + hh)*512 + n)*64) + dd) = v;
      }
    }
  }
}

// ---------------------------------------------------------------------------
// Kernel 2: attention. One block per (b, h, 64-query tile).
// Full 64x512 score row-block in smem; exact two-pass softmax; then P @ V.
// ---------------------------------------------------------------------------
__global__ __launch_bounds__(256, 1) void attn_kernel(
    const float* __restrict__ bias)
{
  extern __shared__ float sm[];
  float* Qt  = sm;                 // [64 d][68] transposed
  float* KVt = sm + 64*68;         // [64][68] (K transposed / V natural)
  float* Ss  = sm + 2*64*68;       // [64][516]

  const int tid = threadIdx.x;
  const int it0 = blockIdx.x * 64;
  const int h   = blockIdx.y;
  const int b   = blockIdx.z;

  const float* Qsrc = g_Q + (((b*8 + h)*512) + it0) * 64;
  const float* Ksrc = g_K + ((b*8 + h)*512) * 64;
  const float* Vsrc = g_V + ((b*8 + h)*512) * 64;

  // load Q tile transposed: Qt[d][i]
#pragma unroll
  for (int itr = 0; itr < 4; itr++) {
    int idx = itr*256 + tid;
    int j = idx >> 4, d4 = (idx & 15) << 2;
    float4 v = *(const float4*)(Qsrc + j*64 + d4);
    Qt[(d4+0)*68 + j] = v.x; Qt[(d4+1)*68 + j] = v.y;
    Qt[(d4+2)*68 + j] = v.z; Qt[(d4+3)*68 + j] = v.w;
  }

  const int ty = tid >> 3;  // 0..31 -> rows ty*2, ty*2+1
  const int tx = tid & 7;   // 0..7  -> cols tx*8 .. tx*8+7
  const bool mi0 = g_mask[b*512 + it0 + ty*2 + 0] != 0;
  const bool mi1 = g_mask[b*512 + it0 + ty*2 + 1] != 0;

  // ---- S = Q K^T * scale + bias, masked ----
  for (int jt = 0; jt < 8; jt++) {
    __syncthreads();
#pragma unroll
    for (int itr = 0; itr < 4; itr++) {
      int idx = itr*256 + tid;
      int j = idx >> 4, d4 = (idx & 15) << 2;
      float4 v = *(const float4*)(Ksrc + (jt*64 + j)*64 + d4);
      KVt[(d4+0)*68 + j] = v.x; KVt[(d4+1)*68 + j] = v.y;
      KVt[(d4+2)*68 + j] = v.z; KVt[(d4+3)*68 + j] = v.w;
    }
    __syncthreads();

    float s0[8], s1[8];
#pragma unroll
    for (int j = 0; j < 8; j++) { s0[j] = 0.f; s1[j] = 0.f; }
#pragma unroll 16
    for (int d = 0; d < 64; d++) {
      float2 aa = *(const float2*)&Qt[d*68 + ty*2];
      float4 b0 = *(const float4*)&KVt[d*68 + tx*8];
      float4 b1 = *(const float4*)&KVt[d*68 + tx*8 + 4];
      float bb[8] = {b0.x,b0.y,b0.z,b0.w,b1.x,b1.y,b1.z,b1.w};
#pragma unroll
      for (int j = 0; j < 8; j++) {
        s0[j] += aa.x * bb[j];
        s1[j] += aa.y * bb[j];
      }
    }

    const float* brow0 = bias + ((h*512 + it0 + ty*2)*512) + jt*64 + tx*8;
    const float* brow1 = brow0 + 512;
    float* srow0 = Ss + (ty*2)*516 + jt*64 + tx*8;
    float* srow1 = srow0 + 516;
#pragma unroll
    for (int jj = 0; jj < 8; jj++) {
      bool mj = g_mask[b*512 + jt*64 + tx*8 + jj] != 0;
      srow0[jj] = (mi0 && mj) ? (s0[jj]*SCALE_ + brow0[jj]) : -FLT_MAX;
      srow1[jj] = (mi1 && mj) ? (s1[jj]*SCALE_ + brow1[jj]) : -FLT_MAX;
    }
  }
  __syncthreads();

  // ---- softmax: warp per 8 rows ----
  {
    const int wid = tid >> 5, lane = tid & 31;
#pragma unroll
    for (int rr = 0; rr < 8; rr++) {
      float* srow = Ss + (wid*8 + rr)*516;
      float4 v[4];
      float mx = -FLT_MAX;
#pragma unroll
      for (int c = 0; c < 4; c++) {
        v[c] = *(float4*)&srow[lane*4 + c*128];
        mx = fmaxf(mx, fmaxf(fmaxf(v[c].x, v[c].y), fmaxf(v[c].z, v[c].w)));
      }
#pragma unroll
      for (int o = 16; o > 0; o >>= 1)
        mx = fmaxf(mx, __shfl_xor_sync(0xffffffffu, mx, o));
      float l = 0.f;
#pragma unroll
      for (int c = 0; c < 4; c++) {
        v[c].x = __expf(v[c].x - mx); v[c].y = __expf(v[c].y - mx);
        v[c].z = __expf(v[c].z - mx); v[c].w = __expf(v[c].w - mx);
        l += v[c].x + v[c].y + v[c].z + v[c].w;
      }
#pragma unroll
      for (int o = 16; o > 0; o >>= 1)
        l += __shfl_xor_sync(0xffffffffu, l, o);
      float inv = 1.0f / l;
#pragma unroll
      for (int c = 0; c < 4; c++) {
        v[c].x *= inv; v[c].y *= inv; v[c].z *= inv; v[c].w *= inv;
        *(float4*)&srow[lane*4 + c*128] = v[c];
      }
    }
  }
  __syncthreads();

  // ---- O = P @ V ----
  float o0[8], o1[8];
#pragma unroll
  for (int j = 0; j < 8; j++) { o0[j] = 0.f; o1[j] = 0.f; }

  for (int jt = 0; jt < 8; jt++) {
#pragma unroll
    for (int itr = 0; itr < 4; itr++) {
      int idx = itr*256 + tid;
      int j = idx >> 4, d4 = (idx & 15) << 2;
      *(float4*)&KVt[j*68 + d4] = *(const float4*)(Vsrc + (jt*64 + j)*64 + d4);
    }
    __syncthreads();
    const float* p0 = Ss + (ty*2)*516 + jt*64;
    const float* p1 = p0 + 516;
#pragma unroll 16
    for (int j = 0; j < 64; j++) {
      float pv0 = p0[j], pv1 = p1[j];
      float4 v0 = *(const float4*)&KVt[j*68 + tx*8];
      float4 v1 = *(const float4*)&KVt[j*68 + tx*8 + 4];
      float vv[8] = {v0.x,v0.y,v0.z,v0.w,v1.x,v1.y,v1.z,v1.w};
#pragma unroll
      for (int jj = 0; jj < 8; jj++) {
        o0[jj] += pv0 * vv[jj];
        o1[jj] += pv1 * vv[jj];
      }
    }
    __syncthreads();
  }

  float* dst0 = g_AO + ((b*512 + it0 + ty*2)*512) + h*64 + tx*8;
  float* dst1 = dst0 + 512;
  *(float4*)(dst0)     = make_float4(o0[0],o0[1],o0[2],o0[3]);
  *(float4*)(dst0 + 4) = make_float4(o0[4],o0[5],o0[6],o0[7]);
  *(float4*)(dst1)     = make_float4(o1[0],o1[1],o1[2],o1[3]);
  *(float4*)(dst1 + 4) = make_float4(o1[4],o1[5],o1[6],o1[7]);
}

// ---------------------------------------------------------------------------
// Kernel 3: Y = (AO .* G) @ Wo + bo.  M=32768, K=512, N=256.
// ---------------------------------------------------------------------------
__global__ __launch_bounds__(256, 2) void out_kernel(
    const float* __restrict__ Wo, const float* __restrict__ bo,
    float* __restrict__ Y)
{
  __shared__ float As[8*132];
  __shared__ float Bs[8*128];
  const int tid = threadIdx.x;
  const int c0 = blockIdx.x * 128;
  const int m0 = blockIdx.y * 128;

  const int arow = tid >> 1, acol = (tid & 1) * 4;
  const int brow = tid >> 5, bcol = (tid & 31) * 4;
  const int tx = tid & 15, ty = tid >> 4;

  float acc[8][8];
#pragma unroll
  for (int i = 0; i < 8; i++)
#pragma unroll
    for (int j = 0; j < 8; j++) acc[i][j] = 0.f;

  const float* aptr = g_AO + (m0 + arow) * 512 + acol;
  const float* gptr = g_G  + (m0 + arow) * 512 + acol;
  const float* bptr = Wo + brow * 256 + c0 + bcol;

  for (int kk = 0; kk < 512; kk += 8) {
    float4 av = *(const float4*)(aptr + kk);
    float4 gv = *(const float4*)(gptr + kk);
    av.x *= gv.x; av.y *= gv.y; av.z *= gv.z; av.w *= gv.w;
    As[(acol+0)*132 + arow] = av.x;
    As[(acol+1)*132 + arow] = av.y;
    As[(acol+2)*132 + arow] = av.z;
    As[(acol+3)*132 + arow] = av.w;
    *(float4*)&Bs[brow*128 + bcol] = *(const float4*)(bptr + kk * 256);
    __syncthreads();
#pragma unroll
    for (int k = 0; k < 8; k++) {
      float4 a0 = *(float4*)&As[k*132 + ty*4];
      float4 a1 = *(float4*)&As[k*132 + 64 + ty*4];
      float4 b0 = *(float4*)&Bs[k*128 + tx*4];
      float4 b1 = *(float4*)&Bs[k*128 + 64 + tx*4];
      float a[8] = {a0.x,a0.y,a0.z,a0.w,a1.x,a1.y,a1.z,a1.w};
      float b[8] = {b0.x,b0.y,b0.z,b0.w,b1.x,b1.y,b1.z,b1.w};
#pragma unroll
      for (int i = 0; i < 8; i++)
#pragma unroll
        for (int j = 0; j < 8; j++) acc[i][j] += a[i]*b[j];
    }
    __syncthreads();
  }

  float4 bo0 = *(const float4*)(bo + c0 + tx*4);
  float4 bo1 = *(const float4*)(bo + c0 + 64 + tx*4);
#pragma unroll
  for (int i = 0; i < 8; i++) {
    int r = (i < 4) ? (ty*4 + i) : (64 + ty*4 + (i - 4));
    int m = m0 + r;
#pragma unroll
    for (int g = 0; g < 2; g++) {
      float4 bv = g ? bo1 : bo0;
      float4 v;
      v.x = acc[i][g*4+0] + bv.x; v.y = acc[i][g*4+1] + bv.y;
      v.z = acc[i][g*4+2] + bv.z; v.w = acc[i][g*4+3] + bv.w;
      *(float4*)(Y + m*256 + c0 + g*64 + tx*4) = v;
    }
  }
}

// ---------------------------------------------------------------------------
extern "C" void kernel_launch(void* const* d_in, const int* in_sizes, int n_in,
                              void* d_out, int out_size)
{
  const float* x   = (const float*)d_in[0];
  const void*  mask = d_in[1];
  const float* bias = (const float*)d_in[2];
  const float* Wq  = (const float*)d_in[3];
  const float* Wkv = (const float*)d_in[4];
  const float* Wo  = (const float*)d_in[5];
  const float* bo  = (const float*)d_in[6];
  const float* Wg  = (const float*)d_in[7];
  const float* bg  = (const float*)d_in[8];
  float* Y = (float*)d_out;

  const int SMEM_ATTN = (2*64*68 + 64*516) * 4;  // 166912 B
  cudaFuncSetAttribute(attn_kernel, cudaFuncAttributeMaxDynamicSharedMemorySize,
                       SMEM_ATTN);

  detect_mask_kernel<<<1, 256>>>((const unsigned int*)mask);
  convert_mask_kernel<<<128, 256>>>(mask);
  proj_kernel<<<dim3(16, 256), 256>>>(x, Wq, Wkv, Wg, bg);
  attn_kernel<<<dim3(8, 8, 64), 256, SMEM_ATTN>>>(bias);
  out_kernel<<<dim3(2, 256), 256>>>(Wo, bo, Y);
}

// round 4
// speedup vs baseline: 1.0628x; 1.0628x over previous
#include <cuda_runtime.h>
#include <cuda_bf16.h>
#include <cfloat>
#include <cstdint>

// Problem constants
#define BB_   64
#define NN_   512
#define DIM_  256
#define HH_   8
#define DHH_  64
#define INNER_ 512
#define SCALE_ 0.125f   // 64^-0.5

// ---------------------------------------------------------------------------
// Scratch (device globals; no allocation allowed)
// ---------------------------------------------------------------------------
__device__ float g_Q[BB_*HH_*NN_*DHH_];   // [b,h,n,d] fp32
__device__ float g_K[BB_*HH_*NN_*DHH_];
__device__ float g_V[BB_*HH_*NN_*DHH_];
__device__ float g_G[BB_*NN_*INNER_];     // gates [m, inner] fp32
__device__ unsigned char g_mask[BB_*NN_];
__device__ int g_mask_mode;

// bf16 split operands
__device__ __nv_bfloat16 g_xh[BB_*NN_*DIM_];    // x hi   [m][256]
__device__ __nv_bfloat16 g_xl[BB_*NN_*DIM_];    // x lo
__device__ __nv_bfloat16 g_Wch[2048*DIM_];      // concat W^T hi [n][256]
__device__ __nv_bfloat16 g_Wcl[2048*DIM_];
__device__ __nv_bfloat16 g_Eh[BB_*NN_*INNER_];  // gated attn out hi [m][512]
__device__ __nv_bfloat16 g_El[BB_*NN_*INNER_];
__device__ __nv_bfloat16 g_Woh[DIM_*INNER_];    // Wo^T hi [n=256][k=512]
__device__ __nv_bfloat16 g_Wol[DIM_*INNER_];

// ---------------------------------------------------------------------------
// Helpers
// ---------------------------------------------------------------------------
__device__ __forceinline__ uint32_t smem_u32(const void* p) {
  uint32_t a;
  asm("{ .reg .u64 t; cvta.to.shared.u64 t, %1; cvt.u32.u64 %0, t; }"
      : "=r"(a) : "l"(p));
  return a;
}

__device__ __forceinline__ void ldsm_x4(uint32_t addr, uint32_t& r0,
                                        uint32_t& r1, uint32_t& r2, uint32_t& r3) {
  asm volatile("ldmatrix.sync.aligned.m8n8.x4.shared.b16 {%0,%1,%2,%3}, [%4];"
               : "=r"(r0), "=r"(r1), "=r"(r2), "=r"(r3) : "r"(addr));
}

__device__ __forceinline__ void mma_bf16(float* c, const uint32_t* a,
                                         const uint32_t* b) {
  asm volatile(
    "mma.sync.aligned.m16n8k16.row.col.f32.bf16.bf16.f32 "
    "{%0,%1,%2,%3}, {%4,%5,%6,%7}, {%8,%9}, {%0,%1,%2,%3};"
    : "+f"(c[0]), "+f"(c[1]), "+f"(c[2]), "+f"(c[3])
    : "r"(a[0]), "r"(a[1]), "r"(a[2]), "r"(a[3]), "r"(b[0]), "r"(b[1]));
}

__device__ __forceinline__ void split2(float v, __nv_bfloat16& h, __nv_bfloat16& l) {
  h = __float2bfloat16(v);
  l = __float2bfloat16(v - __bfloat162float(h));
}

// ---------------------------------------------------------------------------
// Mask dtype detection + canonicalization (proven)
// ---------------------------------------------------------------------------
__global__ void detect_mask_kernel(const unsigned int* __restrict__ m)
{
  __shared__ int s_not01, s_notf;
  if (threadIdx.x == 0) { s_not01 = 0; s_notf = 0; }
  __syncthreads();
  int a = 0, b = 0;
  for (int i = threadIdx.x; i < 8192; i += 256) {
    unsigned v = m[i];
    if (v != 0u && v != 1u) a = 1;
    if (v != 0u && v != 0x3F800000u) b = 1;
  }
  if (a) atomicOr(&s_not01, 1);
  if (b) atomicOr(&s_notf, 1);
  __syncthreads();
  if (threadIdx.x == 0)
    g_mask_mode = (!s_not01) ? 0 : ((!s_notf) ? 1 : 2);
}

__global__ void convert_mask_kernel(const void* __restrict__ m)
{
  int idx = blockIdx.x * blockDim.x + threadIdx.x;
  if (idx >= BB_*NN_) return;
  int mode = g_mask_mode;
  unsigned char r;
  if (mode == 0)      r = ((const int*)m)[idx] != 0;
  else if (mode == 1) r = ((const unsigned int*)m)[idx] != 0u;
  else                r = ((const unsigned char*)m)[idx] != 0;
  g_mask[idx] = r;
}

// ---------------------------------------------------------------------------
// Split conversions
// ---------------------------------------------------------------------------
__global__ void split_x_kernel(const float* __restrict__ x)
{
  int i = (blockIdx.x * 256 + threadIdx.x) * 4;
  float4 v = *(const float4*)(x + i);
  __nv_bfloat16 h[4], l[4];
  split2(v.x, h[0], l[0]); split2(v.y, h[1], l[1]);
  split2(v.z, h[2], l[2]); split2(v.w, h[3], l[3]);
  *(uint2*)(g_xh + i) = *(uint2*)h;
  *(uint2*)(g_xl + i) = *(uint2*)l;
}

__global__ void split_W_kernel(const float* __restrict__ Wq,
                               const float* __restrict__ Wkv,
                               const float* __restrict__ Wg)
{
  int idx = blockIdx.x * 256 + threadIdx.x;   // 2048*256
  int k = idx & 255, n = idx >> 8;
  int seg = n >> 9, col = n & 511;
  float v;
  if (seg == 0)      v = Wq[k*512 + col];
  else if (seg == 1) v = Wkv[k*1024 + col];
  else if (seg == 2) v = Wkv[k*1024 + 512 + col];
  else               v = Wg[k*512 + col];
  __nv_bfloat16 h, l; split2(v, h, l);
  g_Wch[n*256 + k] = h; g_Wcl[n*256 + k] = l;
}

__global__ void split_Wo_kernel(const float* __restrict__ Wo)
{
  int idx = blockIdx.x * 256 + threadIdx.x;   // 256*512
  int n = idx >> 9, k = idx & 511;
  float v = Wo[k*256 + n];
  __nv_bfloat16 h, l; split2(v, h, l);
  g_Woh[n*512 + k] = h; g_Wol[n*512 + k] = l;
}

// ---------------------------------------------------------------------------
// Tile loader: 128 rows x 64 bf16 cols into padded smem (stride 72 elems)
// ---------------------------------------------------------------------------
#define TSTRIDE 72
__device__ __forceinline__ void load_tile(
    __nv_bfloat16* dst, const __nv_bfloat16* __restrict__ src,
    int row0, int col0, int ldk, int tid)
{
#pragma unroll
  for (int it = 0; it < 4; it++) {
    int u = it*256 + tid;          // 1024 8-elem units
    int row = u >> 3, c8 = (u & 7) * 8;
    uint4 v = *(const uint4*)(src + (row0 + row)*ldk + col0 + c8);
    *(uint4*)(dst + row*TSTRIDE + c8) = v;
  }
}

// ---------------------------------------------------------------------------
// Shared GEMM core: block 128x128, 8 warps (4m x 2n), warp tile 32x64.
// 3-term exact bf16 split accumulated into one fp32 fragment set.
// ---------------------------------------------------------------------------
struct FragC { float c[2][8][4]; };

template <int KCHUNKS>
__device__ __forceinline__ void gemm_core(
    __nv_bfloat16* Ah, __nv_bfloat16* Al, __nv_bfloat16* Bh, __nv_bfloat16* Bl,
    const __nv_bfloat16* gAh, const __nv_bfloat16* gAl,
    const __nv_bfloat16* gBh, const __nv_bfloat16* gBl,
    int m0, int n0blk, int ldk, int tid, FragC& f)
{
  const int lane = tid & 31, wid = tid >> 5;
  const int wm = wid & 3, wn = wid >> 2;
  const int lrow = (lane & 7) + ((lane >> 3) & 1) * 8;
  const int lcol = (lane >> 4) * 8;

  const uint32_t ah_base = smem_u32(Ah) + ((wm*32 + lrow)*TSTRIDE + lcol)*2;
  const uint32_t al_base = smem_u32(Al) + ((wm*32 + lrow)*TSTRIDE + lcol)*2;
  const uint32_t bh_base = smem_u32(Bh) + ((wn*64 + lrow)*TSTRIDE + lcol)*2;
  const uint32_t bl_base = smem_u32(Bl) + ((wn*64 + lrow)*TSTRIDE + lcol)*2;

#pragma unroll
  for (int mt = 0; mt < 2; mt++)
#pragma unroll
    for (int nt = 0; nt < 8; nt++)
#pragma unroll
      for (int q = 0; q < 4; q++) f.c[mt][nt][q] = 0.f;

  for (int kc = 0; kc < KCHUNKS; kc++) {
    load_tile(Ah, gAh, m0, kc*64, ldk, tid);
    load_tile(Al, gAl, m0, kc*64, ldk, tid);
    load_tile(Bh, gBh, n0blk, kc*64, ldk, tid);
    load_tile(Bl, gBl, n0blk, kc*64, ldk, tid);
    __syncthreads();

#pragma unroll
    for (int ks = 0; ks < 4; ks++) {
      uint32_t ah[2][4], al[2][4];
#pragma unroll
      for (int mt = 0; mt < 2; mt++) {
        uint32_t off = (mt*16*TSTRIDE + ks*16)*2;
        ldsm_x4(ah_base + off, ah[mt][0], ah[mt][1], ah[mt][2], ah[mt][3]);
        ldsm_x4(al_base + off, al[mt][0], al[mt][1], al[mt][2], al[mt][3]);
      }
      uint32_t bh[8][2], bl[8][2];
#pragma unroll
      for (int np = 0; np < 4; np++) {
        uint32_t off = (np*16*TSTRIDE + ks*16)*2;
        uint32_t r0, r1, r2, r3;
        ldsm_x4(bh_base + off, r0, r1, r2, r3);
        bh[2*np][0] = r0; bh[2*np+1][0] = r1; bh[2*np][1] = r2; bh[2*np+1][1] = r3;
        ldsm_x4(bl_base + off, r0, r1, r2, r3);
        bl[2*np][0] = r0; bl[2*np+1][0] = r1; bl[2*np][1] = r2; bl[2*np+1][1] = r3;
      }
#pragma unroll
      for (int mt = 0; mt < 2; mt++)
#pragma unroll
        for (int nt = 0; nt < 8; nt++) {
          mma_bf16(f.c[mt][nt], ah[mt], bh[nt]);
          mma_bf16(f.c[mt][nt], ah[mt], bl[nt]);
          mma_bf16(f.c[mt][nt], al[mt], bh[nt]);
        }
    }
    __syncthreads();
  }
}

// ---------------------------------------------------------------------------
// Projection GEMM: C[m, c0..c0+128) over K=256; scatter to Q/K/V/G.
// ---------------------------------------------------------------------------
__global__ __launch_bounds__(256) void proj_mma_kernel(const float* __restrict__ bg)
{
  extern __shared__ __nv_bfloat16 smb[];
  __nv_bfloat16* Ah = smb;
  __nv_bfloat16* Al = smb + 128*TSTRIDE;
  __nv_bfloat16* Bh = smb + 2*128*TSTRIDE;
  __nv_bfloat16* Bl = smb + 3*128*TSTRIDE;

  const int tid = threadIdx.x;
  const int c0 = blockIdx.x * 128;
  const int m0 = blockIdx.y * 128;

  FragC f;
  gemm_core<4>(Ah, Al, Bh, Bl, g_xh, g_xl, g_Wch, g_Wcl, m0, c0, 256, tid, f);

  const int lane = tid & 31, wid = tid >> 5;
  const int wm = wid & 3, wn = wid >> 2;
  const int q2 = (lane & 3) * 2, r4 = lane >> 2;
  const int seg = c0 >> 9;
  const int lbase = c0 - seg*512 + wn*64;

#pragma unroll
  for (int mt = 0; mt < 2; mt++) {
#pragma unroll
    for (int h2 = 0; h2 < 2; h2++) {
      const int m = m0 + wm*32 + mt*16 + r4 + h2*8;
      const int bidx = m >> 9, n = m & 511;
      if (seg == 3) {
        float* dst = g_G + m*512 + lbase;
#pragma unroll
        for (int nt = 0; nt < 8; nt++) {
          int cc = nt*8 + q2;
          float2 v;
          v.x = f.c[mt][nt][h2*2+0] + bg[lbase + cc];
          v.y = f.c[mt][nt][h2*2+1] + bg[lbase + cc + 1];
          *(float2*)(dst + cc) = v;
        }
      } else {
        const int hh = lbase >> 6;
        float* base = (seg == 0) ? g_Q : ((seg == 1) ? g_K : g_V);
        float* dst = base + (((bidx*8 + hh)*512 + n)*64);
#pragma unroll
        for (int nt = 0; nt < 8; nt++) {
          int dd = nt*8 + q2;
          float2 v;
          v.x = f.c[mt][nt][h2*2+0];
          v.y = f.c[mt][nt][h2*2+1];
          *(float2*)(dst + dd) = v;
        }
      }
    }
  }
}

// ---------------------------------------------------------------------------
// Output GEMM: Y = E @ Wo^T + bo. M=32768, N=256, K=512.
// ---------------------------------------------------------------------------
__global__ __launch_bounds__(256) void out_mma_kernel(
    const float* __restrict__ bo, float* __restrict__ Y)
{
  extern __shared__ __nv_bfloat16 smb[];
  __nv_bfloat16* Ah = smb;
  __nv_bfloat16* Al = smb + 128*TSTRIDE;
  __nv_bfloat16* Bh = smb + 2*128*TSTRIDE;
  __nv_bfloat16* Bl = smb + 3*128*TSTRIDE;

  const int tid = threadIdx.x;
  const int n0 = blockIdx.x * 128;
  const int m0 = blockIdx.y * 128;

  FragC f;
  gemm_core<8>(Ah, Al, Bh, Bl, g_Eh, g_El, g_Woh, g_Wol, m0, n0, 512, tid, f);

  const int lane = tid & 31, wid = tid >> 5;
  const int wm = wid & 3, wn = wid >> 2;
  const int q2 = (lane & 3) * 2, r4 = lane >> 2;

#pragma unroll
  for (int mt = 0; mt < 2; mt++) {
#pragma unroll
    for (int h2 = 0; h2 < 2; h2++) {
      const int m = m0 + wm*32 + mt*16 + r4 + h2*8;
      float* dst = Y + m*256 + n0 + wn*64;
      const float* bop = bo + n0 + wn*64;
#pragma unroll
      for (int nt = 0; nt < 8; nt++) {
        int cc = nt*8 + q2;
        float2 v;
        v.x = f.c[mt][nt][h2*2+0] + bop[cc];
        v.y = f.c[mt][nt][h2*2+1] + bop[cc + 1];
        *(float2*)(dst + cc) = v;
      }
    }
  }
}

// ---------------------------------------------------------------------------
// Attention (proven scalar core) + gated split-bf16 epilogue.
// ---------------------------------------------------------------------------
__global__ __launch_bounds__(256, 1) void attn_kernel(
    const float* __restrict__ bias)
{
  extern __shared__ float smf[];
  float* Qt  = smf;                 // [64 d][68] transposed
  float* KVt = smf + 64*68;
  float* Ss  = smf + 2*64*68;       // [64][516]

  const int tid = threadIdx.x;
  const int it0 = blockIdx.x * 64;
  const int h   = blockIdx.y;
  const int b   = blockIdx.z;

  const float* Qsrc = g_Q + (((b*8 + h)*512) + it0) * 64;
  const float* Ksrc = g_K + ((b*8 + h)*512) * 64;
  const float* Vsrc = g_V + ((b*8 + h)*512) * 64;

#pragma unroll
  for (int itr = 0; itr < 4; itr++) {
    int idx = itr*256 + tid;
    int j = idx >> 4, d4 = (idx & 15) << 2;
    float4 v = *(const float4*)(Qsrc + j*64 + d4);
    Qt[(d4+0)*68 + j] = v.x; Qt[(d4+1)*68 + j] = v.y;
    Qt[(d4+2)*68 + j] = v.z; Qt[(d4+3)*68 + j] = v.w;
  }

  const int ty = tid >> 3;
  const int tx = tid & 7;
  const bool mi0 = g_mask[b*512 + it0 + ty*2 + 0] != 0;
  const bool mi1 = g_mask[b*512 + it0 + ty*2 + 1] != 0;

  for (int jt = 0; jt < 8; jt++) {
    __syncthreads();
#pragma unroll
    for (int itr = 0; itr < 4; itr++) {
      int idx = itr*256 + tid;
      int j = idx >> 4, d4 = (idx & 15) << 2;
      float4 v = *(const float4*)(Ksrc + (jt*64 + j)*64 + d4);
      KVt[(d4+0)*68 + j] = v.x; KVt[(d4+1)*68 + j] = v.y;
      KVt[(d4+2)*68 + j] = v.z; KVt[(d4+3)*68 + j] = v.w;
    }
    __syncthreads();

    float s0[8], s1[8];
#pragma unroll
    for (int j = 0; j < 8; j++) { s0[j] = 0.f; s1[j] = 0.f; }
#pragma unroll 16
    for (int d = 0; d < 64; d++) {
      float2 aa = *(const float2*)&Qt[d*68 + ty*2];
      float4 b0 = *(const float4*)&KVt[d*68 + tx*8];
      float4 b1 = *(const float4*)&KVt[d*68 + tx*8 + 4];
      float bb[8] = {b0.x,b0.y,b0.z,b0.w,b1.x,b1.y,b1.z,b1.w};
#pragma unroll
      for (int j = 0; j < 8; j++) {
        s0[j] += aa.x * bb[j];
        s1[j] += aa.y * bb[j];
      }
    }

    const float* brow0 = bias + ((h*512 + it0 + ty*2)*512) + jt*64 + tx*8;
    const float* brow1 = brow0 + 512;
    float* srow0 = Ss + (ty*2)*516 + jt*64 + tx*8;
    float* srow1 = srow0 + 516;
#pragma unroll
    for (int jj = 0; jj < 8; jj++) {
      bool mj = g_mask[b*512 + jt*64 + tx*8 + jj] != 0;
      srow0[jj] = (mi0 && mj) ? (s0[jj]*SCALE_ + brow0[jj]) : -FLT_MAX;
      srow1[jj] = (mi1 && mj) ? (s1[jj]*SCALE_ + brow1[jj]) : -FLT_MAX;
    }
  }
  __syncthreads();

  {
    const int wid = tid >> 5, lane = tid & 31;
#pragma unroll
    for (int rr = 0; rr < 8; rr++) {
      float* srow = Ss + (wid*8 + rr)*516;
      float4 v[4];
      float mx = -FLT_MAX;
#pragma unroll
      for (int c = 0; c < 4; c++) {
        v[c] = *(float4*)&srow[lane*4 + c*128];
        mx = fmaxf(mx, fmaxf(fmaxf(v[c].x, v[c].y), fmaxf(v[c].z, v[c].w)));
      }
#pragma unroll
      for (int o = 16; o > 0; o >>= 1)
        mx = fmaxf(mx, __shfl_xor_sync(0xffffffffu, mx, o));
      float l = 0.f;
#pragma unroll
      for (int c = 0; c < 4; c++) {
        v[c].x = __expf(v[c].x - mx); v[c].y = __expf(v[c].y - mx);
        v[c].z = __expf(v[c].z - mx); v[c].w = __expf(v[c].w - mx);
        l += v[c].x + v[c].y + v[c].z + v[c].w;
      }
#pragma unroll
      for (int o = 16; o > 0; o >>= 1)
        l += __shfl_xor_sync(0xffffffffu, l, o);
      float inv = 1.0f / l;
#pragma unroll
      for (int c = 0; c < 4; c++) {
        v[c].x *= inv; v[c].y *= inv; v[c].z *= inv; v[c].w *= inv;
        *(float4*)&srow[lane*4 + c*128] = v[c];
      }
    }
  }
  __syncthreads();

  float o0[8], o1[8];
#pragma unroll
  for (int j = 0; j < 8; j++) { o0[j] = 0.f; o1[j] = 0.f; }

  for (int jt = 0; jt < 8; jt++) {
#pragma unroll
    for (int itr = 0; itr < 4; itr++) {
      int idx = itr*256 + tid;
      int j = idx >> 4, d4 = (idx & 15) << 2;
      *(float4*)&KVt[j*68 + d4] = *(const float4*)(Vsrc + (jt*64 + j)*64 + d4);
    }
    __syncthreads();
    const float* p0 = Ss + (ty*2)*516 + jt*64;
    const float* p1 = p0 + 516;
#pragma unroll 16
    for (int j = 0; j < 64; j++) {
      float pv0 = p0[j], pv1 = p1[j];
      float4 v0 = *(const float4*)&KVt[j*68 + tx*8];
      float4 v1 = *(const float4*)&KVt[j*68 + tx*8 + 4];
      float vv[8] = {v0.x,v0.y,v0.z,v0.w,v1.x,v1.y,v1.z,v1.w};
#pragma unroll
      for (int jj = 0; jj < 8; jj++) {
        o0[jj] += pv0 * vv[jj];
        o1[jj] += pv1 * vv[jj];
      }
    }
    __syncthreads();
  }

  // gated epilogue: E = O * G, split to bf16 hi/lo
  const int idx0 = ((b*512 + it0 + ty*2)*512) + h*64 + tx*8;
  const float* gp0 = g_G + idx0;
  const float* gp1 = gp0 + 512;
  float4 ga = *(const float4*)gp0, gb = *(const float4*)(gp0 + 4);
  float4 gc = *(const float4*)gp1, gd = *(const float4*)(gp1 + 4);
  float gr0[8] = {ga.x,ga.y,ga.z,ga.w,gb.x,gb.y,gb.z,gb.w};
  float gr1[8] = {gc.x,gc.y,gc.z,gc.w,gd.x,gd.y,gd.z,gd.w};

  __align__(16) __nv_bfloat16 h0[8], l0[8], h1[8], l1[8];
#pragma unroll
  for (int j = 0; j < 8; j++) {
    split2(o0[j]*gr0[j], h0[j], l0[j]);
    split2(o1[j]*gr1[j], h1[j], l1[j]);
  }
  *(uint4*)(g_Eh + idx0)       = *(uint4*)h0;
  *(uint4*)(g_El + idx0)       = *(uint4*)l0;
  *(uint4*)(g_Eh + idx0 + 512) = *(uint4*)h1;
  *(uint4*)(g_El + idx0 + 512) = *(uint4*)l1;
}

// ---------------------------------------------------------------------------
extern "C" void kernel_launch(void* const* d_in, const int* in_sizes, int n_in,
                              void* d_out, int out_size)
{
  const float* x   = (const float*)d_in[0];
  const void*  mask = d_in[1];
  const float* bias = (const float*)d_in[2];
  const float* Wq  = (const float*)d_in[3];
  const float* Wkv = (const float*)d_in[4];
  const float* Wo  = (const float*)d_in[5];
  const float* bo  = (const float*)d_in[6];
  const float* Wg  = (const float*)d_in[7];
  const float* bg  = (const float*)d_in[8];
  float* Y = (float*)d_out;

  const int SMEM_ATTN = (2*64*68 + 64*516) * 4;   // 166912 B
  const int SMEM_MMA  = 4 * 128 * TSTRIDE * 2;    // 73728 B
  cudaFuncSetAttribute(attn_kernel, cudaFuncAttributeMaxDynamicSharedMemorySize,
                       SMEM_ATTN);
  cudaFuncSetAttribute(proj_mma_kernel, cudaFuncAttributeMaxDynamicSharedMemorySize,
                       SMEM_MMA);
  cudaFuncSetAttribute(out_mma_kernel, cudaFuncAttributeMaxDynamicSharedMemorySize,
                       SMEM_MMA);

  detect_mask_kernel<<<1, 256>>>((const unsigned int*)mask);
  convert_mask_kernel<<<128, 256>>>(mask);
  split_x_kernel<<<8192, 256>>>(x);
  split_W_kernel<<<2048, 256>>>(Wq, Wkv, Wg);
  split_Wo_kernel<<<512, 256>>>(Wo);
  proj_mma_kernel<<<dim3(16, 256), 256, SMEM_MMA>>>(bg);
  attn_kernel<<<dim3(8, 8, 64), 256, SMEM_ATTN>>>(bias);
  out_mma_kernel<<<dim3(2, 256), 256, SMEM_MMA>>>(bo, Y);
}

// round 5
// speedup vs baseline: 2.4832x; 2.3365x over previous
#include <cuda_runtime.h>
#include <cuda_bf16.h>
#include <cfloat>
#include <cstdint>

// Problem constants
#define BB_   64
#define NN_   512
#define DIM_  256
#define HH_   8
#define DHH_  64
#define INNER_ 512
#define SCALE_ 0.125f   // 64^-0.5

// ---------------------------------------------------------------------------
// Scratch (device globals; no allocation allowed)
// ---------------------------------------------------------------------------
__device__ float g_Q[BB_*HH_*NN_*DHH_];   // [b,h,n,d] fp32
__device__ float g_K[BB_*HH_*NN_*DHH_];
__device__ float g_V[BB_*HH_*NN_*DHH_];
__device__ float g_G[BB_*NN_*INNER_];     // gates [m, inner] fp32
__device__ unsigned char g_mask[BB_*NN_];
__device__ int g_mask_mode;

// bf16 split operands
__device__ __nv_bfloat16 g_xh[BB_*NN_*DIM_];
__device__ __nv_bfloat16 g_xl[BB_*NN_*DIM_];
__device__ __nv_bfloat16 g_Wch[2048*DIM_];
__device__ __nv_bfloat16 g_Wcl[2048*DIM_];
__device__ __nv_bfloat16 g_Eh[BB_*NN_*INNER_];
__device__ __nv_bfloat16 g_El[BB_*NN_*INNER_];
__device__ __nv_bfloat16 g_Woh[DIM_*INNER_];
__device__ __nv_bfloat16 g_Wol[DIM_*INNER_];

// ---------------------------------------------------------------------------
// Helpers
// ---------------------------------------------------------------------------
__device__ __forceinline__ uint32_t smem_u32(const void* p) {
  uint32_t a;
  asm("{ .reg .u64 t; cvta.to.shared.u64 t, %1; cvt.u32.u64 %0, t; }"
      : "=r"(a) : "l"(p));
  return a;
}

__device__ __forceinline__ void ldsm_x4(uint32_t addr, uint32_t& r0,
                                        uint32_t& r1, uint32_t& r2, uint32_t& r3) {
  asm volatile("ldmatrix.sync.aligned.m8n8.x4.shared.b16 {%0,%1,%2,%3}, [%4];"
               : "=r"(r0), "=r"(r1), "=r"(r2), "=r"(r3) : "r"(addr));
}

__device__ __forceinline__ void ldsm_x4_t(uint32_t addr, uint32_t& r0,
                                          uint32_t& r1, uint32_t& r2, uint32_t& r3) {
  asm volatile("ldmatrix.sync.aligned.m8n8.x4.trans.shared.b16 {%0,%1,%2,%3}, [%4];"
               : "=r"(r0), "=r"(r1), "=r"(r2), "=r"(r3) : "r"(addr));
}

__device__ __forceinline__ void mma_bf16(float* c, const uint32_t* a,
                                         const uint32_t* b) {
  asm volatile(
    "mma.sync.aligned.m16n8k16.row.col.f32.bf16.bf16.f32 "
    "{%0,%1,%2,%3}, {%4,%5,%6,%7}, {%8,%9}, {%0,%1,%2,%3};"
    : "+f"(c[0]), "+f"(c[1]), "+f"(c[2]), "+f"(c[3])
    : "r"(a[0]), "r"(a[1]), "r"(a[2]), "r"(a[3]), "r"(b[0]), "r"(b[1]));
}

__device__ __forceinline__ void split2(float v, __nv_bfloat16& h, __nv_bfloat16& l) {
  h = __float2bfloat16(v);
  l = __float2bfloat16(v - __bfloat162float(h));
}

// ---------------------------------------------------------------------------
// Mask dtype detection + canonicalization (proven)
// ---------------------------------------------------------------------------
__global__ void detect_mask_kernel(const unsigned int* __restrict__ m)
{
  __shared__ int s_not01, s_notf;
  if (threadIdx.x == 0) { s_not01 = 0; s_notf = 0; }
  __syncthreads();
  int a = 0, b = 0;
  for (int i = threadIdx.x; i < 8192; i += 256) {
    unsigned v = m[i];
    if (v != 0u && v != 1u) a = 1;
    if (v != 0u && v != 0x3F800000u) b = 1;
  }
  if (a) atomicOr(&s_not01, 1);
  if (b) atomicOr(&s_notf, 1);
  __syncthreads();
  if (threadIdx.x == 0)
    g_mask_mode = (!s_not01) ? 0 : ((!s_notf) ? 1 : 2);
}

__global__ void convert_mask_kernel(const void* __restrict__ m)
{
  int idx = blockIdx.x * blockDim.x + threadIdx.x;
  if (idx >= BB_*NN_) return;
  int mode = g_mask_mode;
  unsigned char r;
  if (mode == 0)      r = ((const int*)m)[idx] != 0;
  else if (mode == 1) r = ((const unsigned int*)m)[idx] != 0u;
  else                r = ((const unsigned char*)m)[idx] != 0;
  g_mask[idx] = r;
}

// ---------------------------------------------------------------------------
// Split conversions
// ---------------------------------------------------------------------------
__global__ void split_x_kernel(const float* __restrict__ x)
{
  int i = (blockIdx.x * 256 + threadIdx.x) * 4;
  float4 v = *(const float4*)(x + i);
  __nv_bfloat16 h[4], l[4];
  split2(v.x, h[0], l[0]); split2(v.y, h[1], l[1]);
  split2(v.z, h[2], l[2]); split2(v.w, h[3], l[3]);
  *(uint2*)(g_xh + i) = *(uint2*)h;
  *(uint2*)(g_xl + i) = *(uint2*)l;
}

__global__ void split_W_kernel(const float* __restrict__ Wq,
                               const float* __restrict__ Wkv,
                               const float* __restrict__ Wg)
{
  int idx = blockIdx.x * 256 + threadIdx.x;   // 2048*256
  int k = idx & 255, n = idx >> 8;
  int seg = n >> 9, col = n & 511;
  float v;
  if (seg == 0)      v = Wq[k*512 + col];
  else if (seg == 1) v = Wkv[k*1024 + col];
  else if (seg == 2) v = Wkv[k*1024 + 512 + col];
  else               v = Wg[k*512 + col];
  __nv_bfloat16 h, l; split2(v, h, l);
  g_Wch[n*256 + k] = h; g_Wcl[n*256 + k] = l;
}

__global__ void split_Wo_kernel(const float* __restrict__ Wo)
{
  int idx = blockIdx.x * 256 + threadIdx.x;   // 256*512
  int n = idx >> 9, k = idx & 511;
  float v = Wo[k*256 + n];
  __nv_bfloat16 h, l; split2(v, h, l);
  g_Woh[n*512 + k] = h; g_Wol[n*512 + k] = l;
}

// ---------------------------------------------------------------------------
// Tile loader for dense GEMMs: 128 rows x 64 bf16 cols (stride 72)
// ---------------------------------------------------------------------------
#define TSTRIDE 72
__device__ __forceinline__ void load_tile(
    __nv_bfloat16* dst, const __nv_bfloat16* __restrict__ src,
    int row0, int col0, int ldk, int tid)
{
#pragma unroll
  for (int it = 0; it < 4; it++) {
    int u = it*256 + tid;
    int row = u >> 3, c8 = (u & 7) * 8;
    uint4 v = *(const uint4*)(src + (row0 + row)*ldk + col0 + c8);
    *(uint4*)(dst + row*TSTRIDE + c8) = v;
  }
}

// ---------------------------------------------------------------------------
// Dense GEMM core (proven): block 128x128, 8 warps (4m x 2n), warp 32x64.
// ---------------------------------------------------------------------------
struct FragC { float c[2][8][4]; };

template <int KCHUNKS>
__device__ __forceinline__ void gemm_core(
    __nv_bfloat16* Ah, __nv_bfloat16* Al, __nv_bfloat16* Bh, __nv_bfloat16* Bl,
    const __nv_bfloat16* gAh, const __nv_bfloat16* gAl,
    const __nv_bfloat16* gBh, const __nv_bfloat16* gBl,
    int m0, int n0blk, int ldk, int tid, FragC& f)
{
  const int lane = tid & 31, wid = tid >> 5;
  const int wm = wid & 3, wn = wid >> 2;
  const int lrow = (lane & 7) + ((lane >> 3) & 1) * 8;
  const int lcol = (lane >> 4) * 8;

  const uint32_t ah_base = smem_u32(Ah) + ((wm*32 + lrow)*TSTRIDE + lcol)*2;
  const uint32_t al_base = smem_u32(Al) + ((wm*32 + lrow)*TSTRIDE + lcol)*2;
  const uint32_t bh_base = smem_u32(Bh) + ((wn*64 + lrow)*TSTRIDE + lcol)*2;
  const uint32_t bl_base = smem_u32(Bl) + ((wn*64 + lrow)*TSTRIDE + lcol)*2;

#pragma unroll
  for (int mt = 0; mt < 2; mt++)
#pragma unroll
    for (int nt = 0; nt < 8; nt++)
#pragma unroll
      for (int q = 0; q < 4; q++) f.c[mt][nt][q] = 0.f;

  for (int kc = 0; kc < KCHUNKS; kc++) {
    load_tile(Ah, gAh, m0, kc*64, ldk, tid);
    load_tile(Al, gAl, m0, kc*64, ldk, tid);
    load_tile(Bh, gBh, n0blk, kc*64, ldk, tid);
    load_tile(Bl, gBl, n0blk, kc*64, ldk, tid);
    __syncthreads();

#pragma unroll
    for (int ks = 0; ks < 4; ks++) {
      uint32_t ah[2][4], al[2][4];
#pragma unroll
      for (int mt = 0; mt < 2; mt++) {
        uint32_t off = (mt*16*TSTRIDE + ks*16)*2;
        ldsm_x4(ah_base + off, ah[mt][0], ah[mt][1], ah[mt][2], ah[mt][3]);
        ldsm_x4(al_base + off, al[mt][0], al[mt][1], al[mt][2], al[mt][3]);
      }
      uint32_t bh[8][2], bl[8][2];
#pragma unroll
      for (int np = 0; np < 4; np++) {
        uint32_t off = (np*16*TSTRIDE + ks*16)*2;
        uint32_t r0, r1, r2, r3;
        ldsm_x4(bh_base + off, r0, r1, r2, r3);
        bh[2*np][0] = r0; bh[2*np+1][0] = r1; bh[2*np][1] = r2; bh[2*np+1][1] = r3;
        ldsm_x4(bl_base + off, r0, r1, r2, r3);
        bl[2*np][0] = r0; bl[2*np+1][0] = r1; bl[2*np][1] = r2; bl[2*np+1][1] = r3;
      }
#pragma unroll
      for (int mt = 0; mt < 2; mt++)
#pragma unroll
        for (int nt = 0; nt < 8; nt++) {
          mma_bf16(f.c[mt][nt], ah[mt], bh[nt]);
          mma_bf16(f.c[mt][nt], ah[mt], bl[nt]);
          mma_bf16(f.c[mt][nt], al[mt], bh[nt]);
        }
    }
    __syncthreads();
  }
}

// ---------------------------------------------------------------------------
// Projection GEMM (proven)
// ---------------------------------------------------------------------------
__global__ __launch_bounds__(256) void proj_mma_kernel(const float* __restrict__ bg)
{
  extern __shared__ __nv_bfloat16 smb[];
  __nv_bfloat16* Ah = smb;
  __nv_bfloat16* Al = smb + 128*TSTRIDE;
  __nv_bfloat16* Bh = smb + 2*128*TSTRIDE;
  __nv_bfloat16* Bl = smb + 3*128*TSTRIDE;

  const int tid = threadIdx.x;
  const int c0 = blockIdx.x * 128;
  const int m0 = blockIdx.y * 128;

  FragC f;
  gemm_core<4>(Ah, Al, Bh, Bl, g_xh, g_xl, g_Wch, g_Wcl, m0, c0, 256, tid, f);

  const int lane = tid & 31, wid = tid >> 5;
  const int wm = wid & 3, wn = wid >> 2;
  const int q2 = (lane & 3) * 2, r4 = lane >> 2;
  const int seg = c0 >> 9;
  const int lbase = c0 - seg*512 + wn*64;

#pragma unroll
  for (int mt = 0; mt < 2; mt++) {
#pragma unroll
    for (int h2 = 0; h2 < 2; h2++) {
      const int m = m0 + wm*32 + mt*16 + r4 + h2*8;
      const int bidx = m >> 9, n = m & 511;
      if (seg == 3) {
        float* dst = g_G + m*512 + lbase;
#pragma unroll
        for (int nt = 0; nt < 8; nt++) {
          int cc = nt*8 + q2;
          float2 v;
          v.x = f.c[mt][nt][h2*2+0] + bg[lbase + cc];
          v.y = f.c[mt][nt][h2*2+1] + bg[lbase + cc + 1];
          *(float2*)(dst + cc) = v;
        }
      } else {
        const int hh = lbase >> 6;
        float* base = (seg == 0) ? g_Q : ((seg == 1) ? g_K : g_V);
        float* dst = base + (((bidx*8 + hh)*512 + n)*64);
#pragma unroll
        for (int nt = 0; nt < 8; nt++) {
          int dd = nt*8 + q2;
          float2 v;
          v.x = f.c[mt][nt][h2*2+0];
          v.y = f.c[mt][nt][h2*2+1];
          *(float2*)(dst + dd) = v;
        }
      }
    }
  }
}

// ---------------------------------------------------------------------------
// Output GEMM (proven)
// ---------------------------------------------------------------------------
__global__ __launch_bounds__(256) void out_mma_kernel(
    const float* __restrict__ bo, float* __restrict__ Y)
{
  extern __shared__ __nv_bfloat16 smb[];
  __nv_bfloat16* Ah = smb;
  __nv_bfloat16* Al = smb + 128*TSTRIDE;
  __nv_bfloat16* Bh = smb + 2*128*TSTRIDE;
  __nv_bfloat16* Bl = smb + 3*128*TSTRIDE;

  const int tid = threadIdx.x;
  const int n0 = blockIdx.x * 128;
  const int m0 = blockIdx.y * 128;

  FragC f;
  gemm_core<8>(Ah, Al, Bh, Bl, g_Eh, g_El, g_Woh, g_Wol, m0, n0, 512, tid, f);

  const int lane = tid & 31, wid = tid >> 5;
  const int wm = wid & 3, wn = wid >> 2;
  const int q2 = (lane & 3) * 2, r4 = lane >> 2;

#pragma unroll
  for (int mt = 0; mt < 2; mt++) {
#pragma unroll
    for (int h2 = 0; h2 < 2; h2++) {
      const int m = m0 + wm*32 + mt*16 + r4 + h2*8;
      float* dst = Y + m*256 + n0 + wn*64;
      const float* bop = bo + n0 + wn*64;
#pragma unroll
      for (int nt = 0; nt < 8; nt++) {
        int cc = nt*8 + q2;
        float2 v;
        v.x = f.c[mt][nt][h2*2+0] + bop[cc];
        v.y = f.c[mt][nt][h2*2+1] + bop[cc + 1];
        *(float2*)(dst + cc) = v;
      }
    }
  }
}

// ---------------------------------------------------------------------------
// Tensor-core attention. Block = (b, h, 64 q-rows). 8 warps (4m x 2n).
// Phase A: S = Q K^T (3-term split), fold scale+bias+mask into softmax,
// Phase B: O = P V (3-term split, ldmatrix.trans for V), gated epilogue.
// smem (bf16 elems): Qh 0, Ql 4608, Kh/Ph 9216, Kl/Pl 13824, Vh 18432,
// Vl 23040; Ss (float) at elem 27648. Total 55296 + 132096 = 187392 B.
// ---------------------------------------------------------------------------
__global__ __launch_bounds__(256, 1) void attn_mma_kernel(
    const float* __restrict__ bias)
{
  extern __shared__ __nv_bfloat16 smb[];
  __nv_bfloat16* Qh = smb;
  __nv_bfloat16* Ql = smb + 4608;
  __nv_bfloat16* Kh = smb + 9216;
  __nv_bfloat16* Kl = smb + 13824;
  __nv_bfloat16* Ph = smb + 9216;   // aliases Kh (phase B)
  __nv_bfloat16* Pl = smb + 13824;  // aliases Kl
  __nv_bfloat16* Vh = smb + 18432;
  __nv_bfloat16* Vl = smb + 23040;
  float* Ss = (float*)(smb + 27648);  // [64][516]

  const int tid = threadIdx.x;
  const int lane = tid & 31, wid = tid >> 5;
  const int wm = wid & 3, wn = wid >> 2;
  const int lrow = (lane & 7) + ((lane >> 3) & 1) * 8;
  const int lcol = (lane >> 4) * 8;
  const int it0 = blockIdx.x * 64;
  const int h = blockIdx.y, b = blockIdx.z;

  const float* Qsrc = g_Q + (((b*8 + h)*512) + it0) * 64;
  const float* Ksrc = g_K + ((b*8 + h)*512) * 64;
  const float* Vsrc = g_V + ((b*8 + h)*512) * 64;

  // Q split load: 64x64
#pragma unroll
  for (int it = 0; it < 4; it++) {
    int u = it*256 + tid;
    int row = u >> 4, d4 = (u & 15) << 2;
    float4 v = *(const float4*)(Qsrc + row*64 + d4);
    __nv_bfloat16 hh[4], ll[4];
    split2(v.x, hh[0], ll[0]); split2(v.y, hh[1], ll[1]);
    split2(v.z, hh[2], ll[2]); split2(v.w, hh[3], ll[3]);
    *(uint2*)(Qh + row*72 + d4) = *(uint2*)hh;
    *(uint2*)(Ql + row*72 + d4) = *(uint2*)ll;
  }

  const uint32_t qh_base = smem_u32(Qh) + ((wm*16 + lrow)*72 + lcol)*2;
  const uint32_t ql_base = smem_u32(Ql) + ((wm*16 + lrow)*72 + lcol)*2;
  const uint32_t kh_base = smem_u32(Kh) + ((wn*32 + lrow)*72 + lcol)*2;
  const uint32_t kl_base = smem_u32(Kl) + ((wn*32 + lrow)*72 + lcol)*2;
  const uint32_t ph_base = qh_base - smem_u32(Qh) + smem_u32(Ph);
  const uint32_t pl_base = qh_base - smem_u32(Qh) + smem_u32(Pl);
  const uint32_t vh_base = smem_u32(Vh) + (lrow*72 + wn*32 + lcol)*2;
  const uint32_t vl_base = smem_u32(Vl) + (lrow*72 + wn*32 + lcol)*2;

  const int r4 = lane >> 2, q2 = (lane & 3) * 2;

  // ---- Phase A: S tiles ----
  for (int jt = 0; jt < 8; jt++) {
    __syncthreads();
#pragma unroll
    for (int it = 0; it < 4; it++) {
      int u = it*256 + tid;
      int row = u >> 4, d4 = (u & 15) << 2;
      float4 v = *(const float4*)(Ksrc + (jt*64 + row)*64 + d4);
      __nv_bfloat16 hh[4], ll[4];
      split2(v.x, hh[0], ll[0]); split2(v.y, hh[1], ll[1]);
      split2(v.z, hh[2], ll[2]); split2(v.w, hh[3], ll[3]);
      *(uint2*)(Kh + row*72 + d4) = *(uint2*)hh;
      *(uint2*)(Kl + row*72 + d4) = *(uint2*)ll;
    }
    __syncthreads();

    float c[4][4];
#pragma unroll
    for (int nf = 0; nf < 4; nf++)
#pragma unroll
      for (int q = 0; q < 4; q++) c[nf][q] = 0.f;

#pragma unroll
    for (int ks = 0; ks < 4; ks++) {
      uint32_t ah[4], al[4];
      ldsm_x4(qh_base + ks*32, ah[0], ah[1], ah[2], ah[3]);
      ldsm_x4(ql_base + ks*32, al[0], al[1], al[2], al[3]);
#pragma unroll
      for (int np = 0; np < 2; np++) {
        uint32_t off = (np*16*72 + ks*16)*2;
        uint32_t r0, r1, r2, r3;
        ldsm_x4(kh_base + off, r0, r1, r2, r3);
        uint32_t bh0[2] = {r0, r2}, bh1[2] = {r1, r3};
        ldsm_x4(kl_base + off, r0, r1, r2, r3);
        uint32_t bl0[2] = {r0, r2}, bl1[2] = {r1, r3};
        mma_bf16(c[2*np],   ah, bh0); mma_bf16(c[2*np],   ah, bl0);
        mma_bf16(c[2*np],   al, bh0);
        mma_bf16(c[2*np+1], ah, bh1); mma_bf16(c[2*np+1], ah, bl1);
        mma_bf16(c[2*np+1], al, bh1);
      }
    }
    // write raw scores to Ss
#pragma unroll
    for (int nf = 0; nf < 4; nf++) {
      int col = jt*64 + wn*32 + nf*8 + q2;
      int row = wm*16 + r4;
      *(float2*)&Ss[row*516 + col]     = make_float2(c[nf][0], c[nf][1]);
      *(float2*)&Ss[(row+8)*516 + col] = make_float2(c[nf][2], c[nf][3]);
    }
  }
  __syncthreads();

  // ---- softmax with scale + bias + mask folded ----
  {
    const unsigned char* mrow = g_mask + b*512;
#pragma unroll
    for (int rr = 0; rr < 8; rr++) {
      int row = wid*8 + rr;
      bool mi = mrow[it0 + row] != 0;
      const float* brow = bias + (h*512 + it0 + row)*512;
      float* srow = Ss + row*516;
      float4 v[4];
      float mx = -FLT_MAX;
#pragma unroll
      for (int cq = 0; cq < 4; cq++) {
        int col = lane*4 + cq*128;
        float4 s = *(float4*)&srow[col];
        float4 bv = *(const float4*)&brow[col];
        uchar4 mj = *(const uchar4*)&mrow[col];
        v[cq].x = (mi && mj.x) ? s.x*SCALE_ + bv.x : -FLT_MAX;
        v[cq].y = (mi && mj.y) ? s.y*SCALE_ + bv.y : -FLT_MAX;
        v[cq].z = (mi && mj.z) ? s.z*SCALE_ + bv.z : -FLT_MAX;
        v[cq].w = (mi && mj.w) ? s.w*SCALE_ + bv.w : -FLT_MAX;
        mx = fmaxf(mx, fmaxf(fmaxf(v[cq].x, v[cq].y), fmaxf(v[cq].z, v[cq].w)));
      }
#pragma unroll
      for (int o = 16; o > 0; o >>= 1)
        mx = fmaxf(mx, __shfl_xor_sync(0xffffffffu, mx, o));
      float l = 0.f;
#pragma unroll
      for (int cq = 0; cq < 4; cq++) {
        v[cq].x = __expf(v[cq].x - mx); v[cq].y = __expf(v[cq].y - mx);
        v[cq].z = __expf(v[cq].z - mx); v[cq].w = __expf(v[cq].w - mx);
        l += v[cq].x + v[cq].y + v[cq].z + v[cq].w;
      }
#pragma unroll
      for (int o = 16; o > 0; o >>= 1)
        l += __shfl_xor_sync(0xffffffffu, l, o);
      float inv = 1.0f / l;
#pragma unroll
      for (int cq = 0; cq < 4; cq++) {
        v[cq].x *= inv; v[cq].y *= inv; v[cq].z *= inv; v[cq].w *= inv;
        *(float4*)&srow[lane*4 + cq*128] = v[cq];
      }
    }
  }

  // ---- Phase B: O = P V ----
  float o[4][4];
#pragma unroll
  for (int nf = 0; nf < 4; nf++)
#pragma unroll
    for (int q = 0; q < 4; q++) o[nf][q] = 0.f;

  for (int jt = 0; jt < 8; jt++) {
    __syncthreads();
    // P chunk convert: rows m, cols j
#pragma unroll
    for (int it = 0; it < 4; it++) {
      int u = it*256 + tid;
      int row = u >> 4, c4 = (u & 15) << 2;
      float4 p = *(float4*)&Ss[row*516 + jt*64 + c4];
      __nv_bfloat16 hh[4], ll[4];
      split2(p.x, hh[0], ll[0]); split2(p.y, hh[1], ll[1]);
      split2(p.z, hh[2], ll[2]); split2(p.w, hh[3], ll[3]);
      *(uint2*)(Ph + row*72 + c4) = *(uint2*)hh;
      *(uint2*)(Pl + row*72 + c4) = *(uint2*)ll;
    }
    // V chunk split (row-major [j][d])
#pragma unroll
    for (int it = 0; it < 4; it++) {
      int u = it*256 + tid;
      int row = u >> 4, d4 = (u & 15) << 2;
      float4 v = *(const float4*)(Vsrc + (jt*64 + row)*64 + d4);
      __nv_bfloat16 hh[4], ll[4];
      split2(v.x, hh[0], ll[0]); split2(v.y, hh[1], ll[1]);
      split2(v.z, hh[2], ll[2]); split2(v.w, hh[3], ll[3]);
      *(uint2*)(Vh + row*72 + d4) = *(uint2*)hh;
      *(uint2*)(Vl + row*72 + d4) = *(uint2*)ll;
    }
    __syncthreads();

#pragma unroll
    for (int ks = 0; ks < 4; ks++) {
      uint32_t ah[4], al[4];
      ldsm_x4(ph_base + ks*32, ah[0], ah[1], ah[2], ah[3]);
      ldsm_x4(pl_base + ks*32, al[0], al[1], al[2], al[3]);
#pragma unroll
      for (int np = 0; np < 2; np++) {
        // trans load from [k=j][n=d]: rows ks*16, cols np*16
        uint32_t off = (ks*16*72 + np*16)*2;
        uint32_t r0, r1, r2, r3;
        ldsm_x4_t(vh_base + off, r0, r1, r2, r3);
        uint32_t bh0[2] = {r0, r1}, bh1[2] = {r2, r3};
        ldsm_x4_t(vl_base + off, r0, r1, r2, r3);
        uint32_t bl0[2] = {r0, r1}, bl1[2] = {r2, r3};
        mma_bf16(o[2*np],   ah, bh0); mma_bf16(o[2*np],   ah, bl0);
        mma_bf16(o[2*np],   al, bh0);
        mma_bf16(o[2*np+1], ah, bh1); mma_bf16(o[2*np+1], ah, bl1);
        mma_bf16(o[2*np+1], al, bh1);
      }
    }
  }

  // ---- gated epilogue: E = O * G, split to bf16 hi/lo ----
#pragma unroll
  for (int nf = 0; nf < 4; nf++) {
    int d = wn*32 + nf*8 + q2;
#pragma unroll
    for (int h2 = 0; h2 < 2; h2++) {
      int row = wm*16 + r4 + h2*8;
      int idx = (b*512 + it0 + row)*512 + h*64 + d;
      float2 gv = *(const float2*)(g_G + idx);
      float e0 = o[nf][h2*2+0] * gv.x;
      float e1 = o[nf][h2*2+1] * gv.y;
      __nv_bfloat16 eh0, el0, eh1, el1;
      split2(e0, eh0, el0); split2(e1, eh1, el1);
      uint32_t ph_, pl_;
      ph_ = (uint32_t)*(uint16_t*)&eh0 | ((uint32_t)*(uint16_t*)&eh1 << 16);
      pl_ = (uint32_t)*(uint16_t*)&el0 | ((uint32_t)*(uint16_t*)&el1 << 16);
      *(uint32_t*)(g_Eh + idx) = ph_;
      *(uint32_t*)(g_El + idx) = pl_;
    }
  }
}

// ---------------------------------------------------------------------------
extern "C" void kernel_launch(void* const* d_in, const int* in_sizes, int n_in,
                              void* d_out, int out_size)
{
  const float* x   = (const float*)d_in[0];
  const void*  mask = d_in[1];
  const float* bias = (const float*)d_in[2];
  const float* Wq  = (const float*)d_in[3];
  const float* Wkv = (const float*)d_in[4];
  const float* Wo  = (const float*)d_in[5];
  const float* bo  = (const float*)d_in[6];
  const float* Wg  = (const float*)d_in[7];
  const float* bg  = (const float*)d_in[8];
  float* Y = (float*)d_out;

  const int SMEM_ATTN = 27648*2 + 64*516*4;       // 187392 B
  const int SMEM_MMA  = 4 * 128 * TSTRIDE * 2;    // 73728 B
  cudaFuncSetAttribute(attn_mma_kernel, cudaFuncAttributeMaxDynamicSharedMemorySize,
                       SMEM_ATTN);
  cudaFuncSetAttribute(proj_mma_kernel, cudaFuncAttributeMaxDynamicSharedMemorySize,
                       SMEM_MMA);
  cudaFuncSetAttribute(out_mma_kernel, cudaFuncAttributeMaxDynamicSharedMemorySize,
                       SMEM_MMA);

  detect_mask_kernel<<<1, 256>>>((const unsigned int*)mask);
  convert_mask_kernel<<<128, 256>>>(mask);
  split_x_kernel<<<8192, 256>>>(x);
  split_W_kernel<<<2048, 256>>>(Wq, Wkv, Wg);
  split_Wo_kernel<<<512, 256>>>(Wo);
  proj_mma_kernel<<<dim3(16, 256), 256, SMEM_MMA>>>(bg);
  attn_mma_kernel<<<dim3(8, 8, 64), 256, SMEM_ATTN>>>(bias);
  out_mma_kernel<<<dim3(2, 256), 256, SMEM_MMA>>>(bo, Y);
}

// round 6
// speedup vs baseline: 2.9301x; 1.1800x over previous
#include <cuda_runtime.h>
#include <cuda_bf16.h>
#include <cfloat>
#include <cstdint>

// Problem constants
#define BB_   64
#define NN_   512
#define DIM_  256
#define HH_   8
#define DHH_  64
#define INNER_ 512
#define SCALE_ 0.125f   // 64^-0.5

// ---------------------------------------------------------------------------
// Scratch (device globals; no allocation allowed)
// ---------------------------------------------------------------------------
__device__ float g_G[BB_*NN_*INNER_];     // gates [m, inner] fp32
__device__ unsigned char g_mask[BB_*NN_];
__device__ int g_mask_mode;

// bf16 split operands
__device__ __nv_bfloat16 g_xh[BB_*NN_*DIM_];
__device__ __nv_bfloat16 g_xl[BB_*NN_*DIM_];
__device__ __nv_bfloat16 g_Wch[2048*DIM_];
__device__ __nv_bfloat16 g_Wcl[2048*DIM_];
__device__ __nv_bfloat16 g_Qh[BB_*HH_*NN_*DHH_];  // [b,h,n,d] split pairs
__device__ __nv_bfloat16 g_Ql[BB_*HH_*NN_*DHH_];
__device__ __nv_bfloat16 g_Kh[BB_*HH_*NN_*DHH_];
__device__ __nv_bfloat16 g_Kl[BB_*HH_*NN_*DHH_];
__device__ __nv_bfloat16 g_Vh[BB_*HH_*NN_*DHH_];
__device__ __nv_bfloat16 g_Vl[BB_*HH_*NN_*DHH_];
__device__ __nv_bfloat16 g_Eh[BB_*NN_*INNER_];
__device__ __nv_bfloat16 g_El[BB_*NN_*INNER_];
__device__ __nv_bfloat16 g_Woh[DIM_*INNER_];
__device__ __nv_bfloat16 g_Wol[DIM_*INNER_];

// ---------------------------------------------------------------------------
// Helpers
// ---------------------------------------------------------------------------
__device__ __forceinline__ uint32_t smem_u32(const void* p) {
  uint32_t a;
  asm("{ .reg .u64 t; cvta.to.shared.u64 t, %1; cvt.u32.u64 %0, t; }"
      : "=r"(a) : "l"(p));
  return a;
}

__device__ __forceinline__ void cp16(uint32_t saddr, const void* g) {
  asm volatile("cp.async.cg.shared.global [%0], [%1], 16;"
               :: "r"(saddr), "l"(g));
}
#define CP_COMMIT() asm volatile("cp.async.commit_group;" ::: "memory")
#define CP_WAIT(n)  asm volatile("cp.async.wait_group %0;" :: "n"(n) : "memory")

__device__ __forceinline__ void ldsm_x4(uint32_t addr, uint32_t& r0,
                                        uint32_t& r1, uint32_t& r2, uint32_t& r3) {
  asm volatile("ldmatrix.sync.aligned.m8n8.x4.shared.b16 {%0,%1,%2,%3}, [%4];"
               : "=r"(r0), "=r"(r1), "=r"(r2), "=r"(r3) : "r"(addr));
}

__device__ __forceinline__ void ldsm_x4_t(uint32_t addr, uint32_t& r0,
                                          uint32_t& r1, uint32_t& r2, uint32_t& r3) {
  asm volatile("ldmatrix.sync.aligned.m8n8.x4.trans.shared.b16 {%0,%1,%2,%3}, [%4];"
               : "=r"(r0), "=r"(r1), "=r"(r2), "=r"(r3) : "r"(addr));
}

__device__ __forceinline__ void mma_bf16(float* c, const uint32_t* a,
                                         const uint32_t* b) {
  asm volatile(
    "mma.sync.aligned.m16n8k16.row.col.f32.bf16.bf16.f32 "
    "{%0,%1,%2,%3}, {%4,%5,%6,%7}, {%8,%9}, {%0,%1,%2,%3};"
    : "+f"(c[0]), "+f"(c[1]), "+f"(c[2]), "+f"(c[3])
    : "r"(a[0]), "r"(a[1]), "r"(a[2]), "r"(a[3]), "r"(b[0]), "r"(b[1]));
}

__device__ __forceinline__ void split2(float v, __nv_bfloat16& h, __nv_bfloat16& l) {
  h = __float2bfloat16(v);
  l = __float2bfloat16(v - __bfloat162float(h));
}

__device__ __forceinline__ uint32_t pack2(__nv_bfloat16 a, __nv_bfloat16 b) {
  return (uint32_t)*(uint16_t*)&a | ((uint32_t)*(uint16_t*)&b << 16);
}

// ---------------------------------------------------------------------------
// Mask dtype detection + canonicalization (proven)
// ---------------------------------------------------------------------------
__global__ void detect_mask_kernel(const unsigned int* __restrict__ m)
{
  __shared__ int s_not01, s_notf;
  if (threadIdx.x == 0) { s_not01 = 0; s_notf = 0; }
  __syncthreads();
  int a = 0, b = 0;
  for (int i = threadIdx.x; i < 8192; i += 256) {
    unsigned v = m[i];
    if (v != 0u && v != 1u) a = 1;
    if (v != 0u && v != 0x3F800000u) b = 1;
  }
  if (a) atomicOr(&s_not01, 1);
  if (b) atomicOr(&s_notf, 1);
  __syncthreads();
  if (threadIdx.x == 0)
    g_mask_mode = (!s_not01) ? 0 : ((!s_notf) ? 1 : 2);
}

__global__ void convert_mask_kernel(const void* __restrict__ m)
{
  int idx = blockIdx.x * blockDim.x + threadIdx.x;
  if (idx >= BB_*NN_) return;
  int mode = g_mask_mode;
  unsigned char r;
  if (mode == 0)      r = ((const int*)m)[idx] != 0;
  else if (mode == 1) r = ((const unsigned int*)m)[idx] != 0u;
  else                r = ((const unsigned char*)m)[idx] != 0;
  g_mask[idx] = r;
}

// ---------------------------------------------------------------------------
// Split conversions
// ---------------------------------------------------------------------------
__global__ void split_x_kernel(const float* __restrict__ x)
{
  int i = (blockIdx.x * 256 + threadIdx.x) * 4;
  float4 v = *(const float4*)(x + i);
  __nv_bfloat16 h[4], l[4];
  split2(v.x, h[0], l[0]); split2(v.y, h[1], l[1]);
  split2(v.z, h[2], l[2]); split2(v.w, h[3], l[3]);
  *(uint2*)(g_xh + i) = *(uint2*)h;
  *(uint2*)(g_xl + i) = *(uint2*)l;
}

__global__ void split_W_kernel(const float* __restrict__ Wq,
                               const float* __restrict__ Wkv,
                               const float* __restrict__ Wg)
{
  int idx = blockIdx.x * 256 + threadIdx.x;   // 2048*256
  int k = idx & 255, n = idx >> 8;
  int seg = n >> 9, col = n & 511;
  float v;
  if (seg == 0)      v = Wq[k*512 + col];
  else if (seg == 1) v = Wkv[k*1024 + col];
  else if (seg == 2) v = Wkv[k*1024 + 512 + col];
  else               v = Wg[k*512 + col];
  __nv_bfloat16 h, l; split2(v, h, l);
  g_Wch[n*256 + k] = h; g_Wcl[n*256 + k] = l;
}

__global__ void split_Wo_kernel(const float* __restrict__ Wo)
{
  int idx = blockIdx.x * 256 + threadIdx.x;   // 256*512
  int n = idx >> 9, k = idx & 511;
  float v = Wo[k*256 + n];
  __nv_bfloat16 h, l; split2(v, h, l);
  g_Woh[n*512 + k] = h; g_Wol[n*512 + k] = l;
}

// ---------------------------------------------------------------------------
// cp.async tile loaders (dst stride 72 elems)
// ---------------------------------------------------------------------------
#define TSTRIDE 72
#define GTILE (128*TSTRIDE)   // 9216 elems per 128-row tile
#define ATILE (64*TSTRIDE)    // 4608 elems per 64-row tile

__device__ __forceinline__ void cpa_tile128(
    __nv_bfloat16* dst, const __nv_bfloat16* __restrict__ src, int ldk, int tid)
{
#pragma unroll
  for (int it = 0; it < 4; it++) {
    int u = it*256 + tid;
    int row = u >> 3, c8 = (u & 7) * 8;
    cp16(smem_u32(dst + row*TSTRIDE + c8), src + row*ldk + c8);
  }
}

__device__ __forceinline__ void cpa_tile64(
    __nv_bfloat16* dst, const __nv_bfloat16* __restrict__ src, int tid)
{
#pragma unroll
  for (int it = 0; it < 2; it++) {
    int u = it*256 + tid;
    int row = u >> 3, c8 = (u & 7) * 8;
    cp16(smem_u32(dst + row*TSTRIDE + c8), src + row*64 + c8);
  }
}

// ---------------------------------------------------------------------------
// Dense GEMM core: block 128x128, 8 warps (4m x 2n), warp 32x64.
// 2-stage cp.async pipeline; 3-term exact bf16 split.
// smem layout (elems): stage s at s*4*GTILE: [Ah, Al, Bh, Bl]
// ---------------------------------------------------------------------------
struct FragC { float c[2][8][4]; };

template <int KCHUNKS>
__device__ __forceinline__ void gemm_core(
    __nv_bfloat16* smb,
    const __nv_bfloat16* gAh, const __nv_bfloat16* gAl,
    const __nv_bfloat16* gBh, const __nv_bfloat16* gBl,
    int m0, int n0blk, int ldk, int tid, FragC& f)
{
  const int lane = tid & 31, wid = tid >> 5;
  const int wm = wid & 3, wn = wid >> 2;
  const int lrow = (lane & 7) + ((lane >> 3) & 1) * 8;
  const int lcol = (lane >> 4) * 8;

  uint32_t abase[2][2], bbase[2][2];
#pragma unroll
  for (int s = 0; s < 2; s++) {
    __nv_bfloat16* st = smb + s*4*GTILE;
    abase[s][0] = smem_u32(st)           + ((wm*32 + lrow)*TSTRIDE + lcol)*2;
    abase[s][1] = smem_u32(st + GTILE)   + ((wm*32 + lrow)*TSTRIDE + lcol)*2;
    bbase[s][0] = smem_u32(st + 2*GTILE) + ((wn*64 + lrow)*TSTRIDE + lcol)*2;
    bbase[s][1] = smem_u32(st + 3*GTILE) + ((wn*64 + lrow)*TSTRIDE + lcol)*2;
  }

#pragma unroll
  for (int mt = 0; mt < 2; mt++)
#pragma unroll
    for (int nt = 0; nt < 8; nt++)
#pragma unroll
      for (int q = 0; q < 4; q++) f.c[mt][nt][q] = 0.f;

  // prefetch chunk 0 -> stage 0
  {
    __nv_bfloat16* st = smb;
    cpa_tile128(st,           gAh + m0*ldk,    ldk, tid);
    cpa_tile128(st + GTILE,   gAl + m0*ldk,    ldk, tid);
    cpa_tile128(st + 2*GTILE, gBh + n0blk*ldk, ldk, tid);
    cpa_tile128(st + 3*GTILE, gBl + n0blk*ldk, ldk, tid);
    CP_COMMIT();
  }

  for (int kc = 0; kc < KCHUNKS; kc++) {
    if (kc + 1 < KCHUNKS) {
      __nv_bfloat16* st = smb + ((kc+1)&1)*4*GTILE;
      int co = (kc+1)*64;
      cpa_tile128(st,           gAh + m0*ldk + co,    ldk, tid);
      cpa_tile128(st + GTILE,   gAl + m0*ldk + co,    ldk, tid);
      cpa_tile128(st + 2*GTILE, gBh + n0blk*ldk + co, ldk, tid);
      cpa_tile128(st + 3*GTILE, gBl + n0blk*ldk + co, ldk, tid);
      CP_COMMIT();
      CP_WAIT(1);
    } else {
      CP_WAIT(0);
    }
    __syncthreads();

    const int s = kc & 1;
#pragma unroll
    for (int ks = 0; ks < 4; ks++) {
      uint32_t ah[2][4], al[2][4];
#pragma unroll
      for (int mt = 0; mt < 2; mt++) {
        uint32_t off = (mt*16*TSTRIDE + ks*16)*2;
        ldsm_x4(abase[s][0] + off, ah[mt][0], ah[mt][1], ah[mt][2], ah[mt][3]);
        ldsm_x4(abase[s][1] + off, al[mt][0], al[mt][1], al[mt][2], al[mt][3]);
      }
      uint32_t bh[8][2], bl[8][2];
#pragma unroll
      for (int np = 0; np < 4; np++) {
        uint32_t off = (np*16*TSTRIDE + ks*16)*2;
        uint32_t r0, r1, r2, r3;
        ldsm_x4(bbase[s][0] + off, r0, r1, r2, r3);
        bh[2*np][0] = r0; bh[2*np+1][0] = r1; bh[2*np][1] = r2; bh[2*np+1][1] = r3;
        ldsm_x4(bbase[s][1] + off, r0, r1, r2, r3);
        bl[2*np][0] = r0; bl[2*np+1][0] = r1; bl[2*np][1] = r2; bl[2*np+1][1] = r3;
      }
#pragma unroll
      for (int mt = 0; mt < 2; mt++)
#pragma unroll
        for (int nt = 0; nt < 8; nt++) {
          mma_bf16(f.c[mt][nt], ah[mt], bh[nt]);
          mma_bf16(f.c[mt][nt], ah[mt], bl[nt]);
          mma_bf16(f.c[mt][nt], al[mt], bh[nt]);
        }
    }
    __syncthreads();
  }
}

// ---------------------------------------------------------------------------
// Projection GEMM: scatters split bf16 Q/K/V and fp32 gates.
// ---------------------------------------------------------------------------
__global__ __launch_bounds__(256) void proj_mma_kernel(const float* __restrict__ bg)
{
  extern __shared__ __nv_bfloat16 smb[];
  const int tid = threadIdx.x;
  const int c0 = blockIdx.x * 128;
  const int m0 = blockIdx.y * 128;

  FragC f;
  gemm_core<4>(smb, g_xh, g_xl, g_Wch, g_Wcl, m0, c0, 256, tid, f);

  const int lane = tid & 31, wid = tid >> 5;
  const int wm = wid & 3, wn = wid >> 2;
  const int q2 = (lane & 3) * 2, r4 = lane >> 2;
  const int seg = c0 >> 9;
  const int lbase = c0 - seg*512 + wn*64;

#pragma unroll
  for (int mt = 0; mt < 2; mt++) {
#pragma unroll
    for (int h2 = 0; h2 < 2; h2++) {
      const int m = m0 + wm*32 + mt*16 + r4 + h2*8;
      const int bidx = m >> 9, n = m & 511;
      if (seg == 3) {
        float* dst = g_G + m*512 + lbase;
#pragma unroll
        for (int nt = 0; nt < 8; nt++) {
          int cc = nt*8 + q2;
          float2 v;
          v.x = f.c[mt][nt][h2*2+0] + bg[lbase + cc];
          v.y = f.c[mt][nt][h2*2+1] + bg[lbase + cc + 1];
          *(float2*)(dst + cc) = v;
        }
      } else {
        const int hh = lbase >> 6;
        __nv_bfloat16 *bh_, *bl_;
        if (seg == 0)      { bh_ = g_Qh; bl_ = g_Ql; }
        else if (seg == 1) { bh_ = g_Kh; bl_ = g_Kl; }
        else               { bh_ = g_Vh; bl_ = g_Vl; }
        const int off = (((bidx*8 + hh)*512 + n)*64);
#pragma unroll
        for (int nt = 0; nt < 8; nt++) {
          int dd = nt*8 + q2;
          __nv_bfloat16 h0, l0, h1, l1;
          split2(f.c[mt][nt][h2*2+0], h0, l0);
          split2(f.c[mt][nt][h2*2+1], h1, l1);
          *(uint32_t*)(bh_ + off + dd) = pack2(h0, h1);
          *(uint32_t*)(bl_ + off + dd) = pack2(l0, l1);
        }
      }
    }
  }
}

// ---------------------------------------------------------------------------
// Output GEMM: Y = E @ Wo^T + bo
// ---------------------------------------------------------------------------
__global__ __launch_bounds__(256) void out_mma_kernel(
    const float* __restrict__ bo, float* __restrict__ Y)
{
  extern __shared__ __nv_bfloat16 smb[];
  const int tid = threadIdx.x;
  const int n0 = blockIdx.x * 128;
  const int m0 = blockIdx.y * 128;

  FragC f;
  gemm_core<8>(smb, g_Eh, g_El, g_Woh, g_Wol, m0, n0, 512, tid, f);

  const int lane = tid & 31, wid = tid >> 5;
  const int wm = wid & 3, wn = wid >> 2;
  const int q2 = (lane & 3) * 2, r4 = lane >> 2;

#pragma unroll
  for (int mt = 0; mt < 2; mt++) {
#pragma unroll
    for (int h2 = 0; h2 < 2; h2++) {
      const int m = m0 + wm*32 + mt*16 + r4 + h2*8;
      float* dst = Y + m*256 + n0 + wn*64;
      const float* bop = bo + n0 + wn*64;
#pragma unroll
      for (int nt = 0; nt < 8; nt++) {
        int cc = nt*8 + q2;
        float2 v;
        v.x = f.c[mt][nt][h2*2+0] + bop[cc];
        v.y = f.c[mt][nt][h2*2+1] + bop[cc + 1];
        *(float2*)(dst + cc) = v;
      }
    }
  }
}

// ---------------------------------------------------------------------------
// Tensor-core attention with pre-split bf16 Q/K/V and cp.async pipelines.
// smem tiles (bf16, ATILE=4608): Qh@0 / Ql@4608 (phase B: Ph/Pl)
//   stage0 h@9216 l@13824, stage1 h@18432 l@23040 (K in phase A, V in phase B)
//   Ss float at elem 27648: [64][516]
// ---------------------------------------------------------------------------
__global__ __launch_bounds__(256, 1) void attn_mma_kernel(
    const float* __restrict__ bias)
{
  extern __shared__ __nv_bfloat16 smb[];
  __nv_bfloat16* Qh = smb;
  __nv_bfloat16* Ql = smb + ATILE;
  __nv_bfloat16* St[2][2] = {{smb + 2*ATILE, smb + 3*ATILE},
                             {smb + 4*ATILE, smb + 5*ATILE}};
  float* Ss = (float*)(smb + 6*ATILE);  // [64][516]

  const int tid = threadIdx.x;
  const int lane = tid & 31, wid = tid >> 5;
  const int wm = wid & 3, wn = wid >> 2;
  const int lrow = (lane & 7) + ((lane >> 3) & 1) * 8;
  const int lcol = (lane >> 4) * 8;
  const int it0 = blockIdx.x * 64;
  const int h = blockIdx.y, b = blockIdx.z;

  const int bh_off = (b*8 + h) * 512 * 64;
  const __nv_bfloat16* Qhs = g_Qh + bh_off + it0*64;
  const __nv_bfloat16* Qls = g_Ql + bh_off + it0*64;
  const __nv_bfloat16* Khs = g_Kh + bh_off;
  const __nv_bfloat16* Kls = g_Kl + bh_off;
  const __nv_bfloat16* Vhs = g_Vh + bh_off;
  const __nv_bfloat16* Vls = g_Vl + bh_off;

  // prefetch Q tiles + K chunk 0 (one group)
  cpa_tile64(Qh, Qhs, tid);
  cpa_tile64(Ql, Qls, tid);
  cpa_tile64(St[0][0], Khs, tid);
  cpa_tile64(St[0][1], Kls, tid);
  CP_COMMIT();

  const uint32_t qh_base = smem_u32(Qh) + ((wm*16 + lrow)*TSTRIDE + lcol)*2;
  const uint32_t ql_base = smem_u32(Ql) + ((wm*16 + lrow)*TSTRIDE + lcol)*2;
  uint32_t kb[2][2], vb[2][2];
#pragma unroll
  for (int s = 0; s < 2; s++) {
    kb[s][0] = smem_u32(St[s][0]) + ((wn*32 + lrow)*TSTRIDE + lcol)*2;
    kb[s][1] = smem_u32(St[s][1]) + ((wn*32 + lrow)*TSTRIDE + lcol)*2;
    vb[s][0] = smem_u32(St[s][0]) + (lrow*TSTRIDE + wn*32 + lcol)*2;
    vb[s][1] = smem_u32(St[s][1]) + (lrow*TSTRIDE + wn*32 + lcol)*2;
  }

  const int r4 = lane >> 2, q2 = (lane & 3) * 2;

  // ---- Phase A: S = Q K^T ----
  for (int jt = 0; jt < 8; jt++) {
    if (jt < 7) {
      const int s = (jt+1) & 1;
      cpa_tile64(St[s][0], Khs + (jt+1)*64*64, tid);
      cpa_tile64(St[s][1], Kls + (jt+1)*64*64, tid);
      CP_COMMIT();
      CP_WAIT(1);
    } else {
      CP_WAIT(0);
    }
    __syncthreads();

    const int s = jt & 1;
    float c[4][4];
#pragma unroll
    for (int nf = 0; nf < 4; nf++)
#pragma unroll
      for (int q = 0; q < 4; q++) c[nf][q] = 0.f;

#pragma unroll
    for (int ks = 0; ks < 4; ks++) {
      uint32_t ah[4], al[4];
      ldsm_x4(qh_base + ks*32, ah[0], ah[1], ah[2], ah[3]);
      ldsm_x4(ql_base + ks*32, al[0], al[1], al[2], al[3]);
#pragma unroll
      for (int np = 0; np < 2; np++) {
        uint32_t off = (np*16*TSTRIDE + ks*16)*2;
        uint32_t r0, r1, r2, r3;
        ldsm_x4(kb[s][0] + off, r0, r1, r2, r3);
        uint32_t bh0[2] = {r0, r2}, bh1[2] = {r1, r3};
        ldsm_x4(kb[s][1] + off, r0, r1, r2, r3);
        uint32_t bl0[2] = {r0, r2}, bl1[2] = {r1, r3};
        mma_bf16(c[2*np],   ah, bh0); mma_bf16(c[2*np],   ah, bl0);
        mma_bf16(c[2*np],   al, bh0);
        mma_bf16(c[2*np+1], ah, bh1); mma_bf16(c[2*np+1], ah, bl1);
        mma_bf16(c[2*np+1], al, bh1);
      }
    }
#pragma unroll
    for (int nf = 0; nf < 4; nf++) {
      int col = jt*64 + wn*32 + nf*8 + q2;
      int row = wm*16 + r4;
      *(float2*)&Ss[row*516 + col]     = make_float2(c[nf][0], c[nf][1]);
      *(float2*)&Ss[(row+8)*516 + col] = make_float2(c[nf][2], c[nf][3]);
    }
    __syncthreads();
  }

  // prefetch V chunk 0 (overlaps softmax)
  cpa_tile64(St[0][0], Vhs, tid);
  cpa_tile64(St[0][1], Vls, tid);
  CP_COMMIT();

  // ---- softmax with scale + bias + mask folded ----
  {
    const unsigned char* mrow = g_mask + b*512;
#pragma unroll
    for (int rr = 0; rr < 8; rr++) {
      int row = wid*8 + rr;
      bool mi = mrow[it0 + row] != 0;
      const float* brow = bias + (h*512 + it0 + row)*512;
      float* srow = Ss + row*516;
      float4 v[4];
      float mx = -FLT_MAX;
#pragma unroll
      for (int cq = 0; cq < 4; cq++) {
        int col = lane*4 + cq*128;
        float4 sv = *(float4*)&srow[col];
        float4 bv = *(const float4*)&brow[col];
        uchar4 mj = *(const uchar4*)&mrow[col];
        v[cq].x = (mi && mj.x) ? sv.x*SCALE_ + bv.x : -FLT_MAX;
        v[cq].y = (mi && mj.y) ? sv.y*SCALE_ + bv.y : -FLT_MAX;
        v[cq].z = (mi && mj.z) ? sv.z*SCALE_ + bv.z : -FLT_MAX;
        v[cq].w = (mi && mj.w) ? sv.w*SCALE_ + bv.w : -FLT_MAX;
        mx = fmaxf(mx, fmaxf(fmaxf(v[cq].x, v[cq].y), fmaxf(v[cq].z, v[cq].w)));
      }
#pragma unroll
      for (int o = 16; o > 0; o >>= 1)
        mx = fmaxf(mx, __shfl_xor_sync(0xffffffffu, mx, o));
      float l = 0.f;
#pragma unroll
      for (int cq = 0; cq < 4; cq++) {
        v[cq].x = __expf(v[cq].x - mx); v[cq].y = __expf(v[cq].y - mx);
        v[cq].z = __expf(v[cq].z - mx); v[cq].w = __expf(v[cq].w - mx);
        l += v[cq].x + v[cq].y + v[cq].z + v[cq].w;
      }
#pragma unroll
      for (int o = 16; o > 0; o >>= 1)
        l += __shfl_xor_sync(0xffffffffu, l, o);
      float inv = 1.0f / l;
#pragma unroll
      for (int cq = 0; cq < 4; cq++) {
        v[cq].x *= inv; v[cq].y *= inv; v[cq].z *= inv; v[cq].w *= inv;
        *(float4*)&srow[lane*4 + cq*128] = v[cq];
      }
    }
  }
  __syncthreads();

  // ---- Phase B: O = P V (P aliases Q tiles) ----
  __nv_bfloat16* Ph = Qh;
  __nv_bfloat16* Pl = Ql;
  float o[4][4];
#pragma unroll
  for (int nf = 0; nf < 4; nf++)
#pragma unroll
    for (int q = 0; q < 4; q++) o[nf][q] = 0.f;

  for (int jt = 0; jt < 8; jt++) {
    if (jt < 7) {
      const int s = (jt+1) & 1;
      cpa_tile64(St[s][0], Vhs + (jt+1)*64*64, tid);
      cpa_tile64(St[s][1], Vls + (jt+1)*64*64, tid);
      CP_COMMIT();
    }
    // convert P chunk jt (overlaps V load latency)
#pragma unroll
    for (int it = 0; it < 4; it++) {
      int u = it*256 + tid;
      int row = u >> 4, c4 = (u & 15) << 2;
      float4 p = *(float4*)&Ss[row*516 + jt*64 + c4];
      __nv_bfloat16 hh[4], ll[4];
      split2(p.x, hh[0], ll[0]); split2(p.y, hh[1], ll[1]);
      split2(p.z, hh[2], ll[2]); split2(p.w, hh[3], ll[3]);
      *(uint2*)(Ph + row*TSTRIDE + c4) = *(uint2*)hh;
      *(uint2*)(Pl + row*TSTRIDE + c4) = *(uint2*)ll;
    }
    if (jt < 7) { CP_WAIT(1); } else { CP_WAIT(0); }
    __syncthreads();

    const int s = jt & 1;
#pragma unroll
    for (int ks = 0; ks < 4; ks++) {
      uint32_t ah[4], al[4];
      ldsm_x4(qh_base + ks*32, ah[0], ah[1], ah[2], ah[3]);
      ldsm_x4(ql_base + ks*32, al[0], al[1], al[2], al[3]);
#pragma unroll
      for (int np = 0; np < 2; np++) {
        uint32_t off = (ks*16*TSTRIDE + np*16)*2;
        uint32_t r0, r1, r2, r3;
        ldsm_x4_t(vb[s][0] + off, r0, r1, r2, r3);
        uint32_t bh0[2] = {r0, r1}, bh1[2] = {r2, r3};
        ldsm_x4_t(vb[s][1] + off, r0, r1, r2, r3);
        uint32_t bl0[2] = {r0, r1}, bl1[2] = {r2, r3};
        mma_bf16(o[2*np],   ah, bh0); mma_bf16(o[2*np],   ah, bl0);
        mma_bf16(o[2*np],   al, bh0);
        mma_bf16(o[2*np+1], ah, bh1); mma_bf16(o[2*np+1], ah, bl1);
        mma_bf16(o[2*np+1], al, bh1);
      }
    }
    __syncthreads();
  }

  // ---- gated epilogue: E = O * G, split to bf16 hi/lo ----
#pragma unroll
  for (int nf = 0; nf < 4; nf++) {
    int d = wn*32 + nf*8 + q2;
#pragma unroll
    for (int h2 = 0; h2 < 2; h2++) {
      int row = wm*16 + r4 + h2*8;
      int idx = (b*512 + it0 + row)*512 + h*64 + d;
      float2 gv = *(const float2*)(g_G + idx);
      float e0 = o[nf][h2*2+0] * gv.x;
      float e1 = o[nf][h2*2+1] * gv.y;
      __nv_bfloat16 eh0, el0, eh1, el1;
      split2(e0, eh0, el0); split2(e1, eh1, el1);
      *(uint32_t*)(g_Eh + idx) = pack2(eh0, eh1);
      *(uint32_t*)(g_El + idx) = pack2(el0, el1);
    }
  }
}

// ---------------------------------------------------------------------------
extern "C" void kernel_launch(void* const* d_in, const int* in_sizes, int n_in,
                              void* d_out, int out_size)
{
  const float* x   = (const float*)d_in[0];
  const void*  mask = d_in[1];
  const float* bias = (const float*)d_in[2];
  const float* Wq  = (const float*)d_in[3];
  const float* Wkv = (const float*)d_in[4];
  const float* Wo  = (const float*)d_in[5];
  const float* bo  = (const float*)d_in[6];
  const float* Wg  = (const float*)d_in[7];
  const float* bg  = (const float*)d_in[8];
  float* Y = (float*)d_out;

  const int SMEM_ATTN = 6*ATILE*2 + 64*516*4;     // 55296 + 132096 = 187392 B
  const int SMEM_MMA  = 8 * GTILE * 2;            // 147456 B
  cudaFuncSetAttribute(attn_mma_kernel, cudaFuncAttributeMaxDynamicSharedMemorySize,
                       SMEM_ATTN);
  cudaFuncSetAttribute(proj_mma_kernel, cudaFuncAttributeMaxDynamicSharedMemorySize,
                       SMEM_MMA);
  cudaFuncSetAttribute(out_mma_kernel, cudaFuncAttributeMaxDynamicSharedMemorySize,
                       SMEM_MMA);

  detect_mask_kernel<<<1, 256>>>((const unsigned int*)mask);
  convert_mask_kernel<<<128, 256>>>(mask);
  split_x_kernel<<<8192, 256>>>(x);
  split_W_kernel<<<2048, 256>>>(Wq, Wkv, Wg);
  split_Wo_kernel<<<512, 256>>>(Wo);
  proj_mma_kernel<<<dim3(16, 256), 256, SMEM_MMA>>>(bg);
  attn_mma_kernel<<<dim3(8, 8, 64), 256, SMEM_ATTN>>>(bias);
  out_mma_kernel<<<dim3(2, 256), 256, SMEM_MMA>>>(bo, Y);
}

// round 8
// speedup vs baseline: 3.6360x; 1.2409x over previous
#include <cuda_runtime.h>
#include <cuda_bf16.h>
#include <cfloat>
#include <cstdint>

#define BB_   64
#define NN_   512
#define DIM_  256
#define HH_   8
#define DHH_  64
#define INNER_ 512
#define SCALE_ 0.125f

// ---------------------------------------------------------------------------
// Scratch
// ---------------------------------------------------------------------------
__device__ float g_G[BB_*NN_*INNER_];
__device__ unsigned char g_mask[BB_*NN_];
__device__ int g_mask_mode;

__device__ __nv_bfloat16 g_xh[BB_*NN_*DIM_];
__device__ __nv_bfloat16 g_xl[BB_*NN_*DIM_];
__device__ __nv_bfloat16 g_Wch[2048*DIM_];
__device__ __nv_bfloat16 g_Wcl[2048*DIM_];
__device__ __nv_bfloat16 g_Qh[BB_*HH_*NN_*DHH_];
__device__ __nv_bfloat16 g_Ql[BB_*HH_*NN_*DHH_];
__device__ __nv_bfloat16 g_Kh[BB_*HH_*NN_*DHH_];
__device__ __nv_bfloat16 g_Kl[BB_*HH_*NN_*DHH_];
__device__ __nv_bfloat16 g_Vh[BB_*HH_*NN_*DHH_];
__device__ __nv_bfloat16 g_Vl[BB_*HH_*NN_*DHH_];
__device__ __nv_bfloat16 g_Eh[BB_*NN_*INNER_];
__device__ __nv_bfloat16 g_El[BB_*NN_*INNER_];
__device__ __nv_bfloat16 g_Woh[DIM_*INNER_];
__device__ __nv_bfloat16 g_Wol[DIM_*INNER_];

// ---------------------------------------------------------------------------
// Helpers
// ---------------------------------------------------------------------------
__device__ __forceinline__ uint32_t smem_u32(const void* p) {
  uint32_t a;
  asm("{ .reg .u64 t; cvta.to.shared.u64 t, %1; cvt.u32.u64 %0, t; }"
      : "=r"(a) : "l"(p));
  return a;
}
__device__ __forceinline__ void cp16(uint32_t saddr, const void* g) {
  asm volatile("cp.async.cg.shared.global [%0], [%1], 16;"
               :: "r"(saddr), "l"(g));
}
#define CP_COMMIT() asm volatile("cp.async.commit_group;" ::: "memory")
#define CP_WAIT(n)  asm volatile("cp.async.wait_group %0;" :: "n"(n) : "memory")

__device__ __forceinline__ void ldsm_x4(uint32_t addr, uint32_t& r0,
                                        uint32_t& r1, uint32_t& r2, uint32_t& r3) {
  asm volatile("ldmatrix.sync.aligned.m8n8.x4.shared.b16 {%0,%1,%2,%3}, [%4];"
               : "=r"(r0), "=r"(r1), "=r"(r2), "=r"(r3) : "r"(addr));
}
__device__ __forceinline__ void ldsm_x4_t(uint32_t addr, uint32_t& r0,
                                          uint32_t& r1, uint32_t& r2, uint32_t& r3) {
  asm volatile("ldmatrix.sync.aligned.m8n8.x4.trans.shared.b16 {%0,%1,%2,%3}, [%4];"
               : "=r"(r0), "=r"(r1), "=r"(r2), "=r"(r3) : "r"(addr));
}
__device__ __forceinline__ void mma_bf16(float* c, const uint32_t* a,
                                         const uint32_t* b) {
  asm volatile(
    "mma.sync.aligned.m16n8k16.row.col.f32.bf16.bf16.f32 "
    "{%0,%1,%2,%3}, {%4,%5,%6,%7}, {%8,%9}, {%0,%1,%2,%3};"
    : "+f"(c[0]), "+f"(c[1]), "+f"(c[2]), "+f"(c[3])
    : "r"(a[0]), "r"(a[1]), "r"(a[2]), "r"(a[3]), "r"(b[0]), "r"(b[1]));
}
__device__ __forceinline__ void split2(float v, __nv_bfloat16& h, __nv_bfloat16& l) {
  h = __float2bfloat16(v);
  l = __float2bfloat16(v - __bfloat162float(h));
}
__device__ __forceinline__ uint32_t pack2(__nv_bfloat16 a, __nv_bfloat16 b) {
  return (uint32_t)*(uint16_t*)&a | ((uint32_t)*(uint16_t*)&b << 16);
}

// ---------------------------------------------------------------------------
// Mask detection + conversion (proven)
// ---------------------------------------------------------------------------
__global__ void detect_mask_kernel(const unsigned int* __restrict__ m)
{
  __shared__ int s_not01, s_notf;
  if (threadIdx.x == 0) { s_not01 = 0; s_notf = 0; }
  __syncthreads();
  int a = 0, b = 0;
  for (int i = threadIdx.x; i < 8192; i += 256) {
    unsigned v = m[i];
    if (v != 0u && v != 1u) a = 1;
    if (v != 0u && v != 0x3F800000u) b = 1;
  }
  if (a) atomicOr(&s_not01, 1);
  if (b) atomicOr(&s_notf, 1);
  __syncthreads();
  if (threadIdx.x == 0)
    g_mask_mode = (!s_not01) ? 0 : ((!s_notf) ? 1 : 2);
}

__global__ void convert_mask_kernel(const void* __restrict__ m)
{
  int idx = blockIdx.x * blockDim.x + threadIdx.x;
  if (idx >= BB_*NN_) return;
  int mode = g_mask_mode;
  unsigned char r;
  if (mode == 0)      r = ((const int*)m)[idx] != 0;
  else if (mode == 1) r = ((const unsigned int*)m)[idx] != 0u;
  else                r = ((const unsigned char*)m)[idx] != 0;
  g_mask[idx] = r;
}

// ---------------------------------------------------------------------------
// Split conversions (proven)
// ---------------------------------------------------------------------------
__global__ void split_x_kernel(const float* __restrict__ x)
{
  int i = (blockIdx.x * 256 + threadIdx.x) * 4;
  float4 v = *(const float4*)(x + i);
  __nv_bfloat16 h[4], l[4];
  split2(v.x, h[0], l[0]); split2(v.y, h[1], l[1]);
  split2(v.z, h[2], l[2]); split2(v.w, h[3], l[3]);
  *(uint2*)(g_xh + i) = *(uint2*)h;
  *(uint2*)(g_xl + i) = *(uint2*)l;
}

__global__ void split_W_kernel(const float* __restrict__ Wq,
                               const float* __restrict__ Wkv,
                               const float* __restrict__ Wg)
{
  int idx = blockIdx.x * 256 + threadIdx.x;
  int k = idx & 255, n = idx >> 8;
  int seg = n >> 9, col = n & 511;
  float v;
  if (seg == 0)      v = Wq[k*512 + col];
  else if (seg == 1) v = Wkv[k*1024 + col];
  else if (seg == 2) v = Wkv[k*1024 + 512 + col];
  else               v = Wg[k*512 + col];
  __nv_bfloat16 h, l; split2(v, h, l);
  g_Wch[n*256 + k] = h; g_Wcl[n*256 + k] = l;
}

__global__ void split_Wo_kernel(const float* __restrict__ Wo)
{
  int idx = blockIdx.x * 256 + threadIdx.x;
  int n = idx >> 9, k = idx & 511;
  float v = Wo[k*256 + n];
  __nv_bfloat16 h, l; split2(v, h, l);
  g_Woh[n*512 + k] = h; g_Wol[n*512 + k] = l;
}

// ---------------------------------------------------------------------------
// Tile loaders
// ---------------------------------------------------------------------------
#define TSTRIDE 72
#define GTILE (128*TSTRIDE)
#define ATILE (64*TSTRIDE)

__device__ __forceinline__ void cpa_tile128_512(
    __nv_bfloat16* dst, const __nv_bfloat16* __restrict__ src, int ldk, int tid)
{
#pragma unroll
  for (int it = 0; it < 2; it++) {
    int u = it*512 + tid;
    int row = u >> 3, c8 = (u & 7) * 8;
    cp16(smem_u32(dst + row*TSTRIDE + c8), src + row*ldk + c8);
  }
}

__device__ __forceinline__ void cpa_tile64(
    __nv_bfloat16* dst, const __nv_bfloat16* __restrict__ src, int tid)
{
#pragma unroll
  for (int it = 0; it < 2; it++) {
    int u = it*256 + tid;
    int row = u >> 3, c8 = (u & 7) * 8;
    cp16(smem_u32(dst + row*TSTRIDE + c8), src + row*64 + c8);
  }
}

// ---------------------------------------------------------------------------
// Dense GEMM core: block 128x128, 16 warps (4m x 4n), warp tile 32x32.
// ---------------------------------------------------------------------------
struct FragC { float c[2][4][4]; };

template <int KCHUNKS>
__device__ __forceinline__ void gemm_core(
    __nv_bfloat16* smb,
    const __nv_bfloat16* gAh, const __nv_bfloat16* gAl,
    const __nv_bfloat16* gBh, const __nv_bfloat16* gBl,
    int m0, int n0blk, int ldk, int tid, FragC& f)
{
  const int lane = tid & 31, wid = tid >> 5;
  const int wm = wid & 3, wn = wid >> 2;
  const int lrow = (lane & 7) + ((lane >> 3) & 1) * 8;
  const int lcol = (lane >> 4) * 8;

  uint32_t abase[2][2], bbase[2][2];
#pragma unroll
  for (int s = 0; s < 2; s++) {
    __nv_bfloat16* st = smb + s*4*GTILE;
    abase[s][0] = smem_u32(st)           + ((wm*32 + lrow)*TSTRIDE + lcol)*2;
    abase[s][1] = smem_u32(st + GTILE)   + ((wm*32 + lrow)*TSTRIDE + lcol)*2;
    bbase[s][0] = smem_u32(st + 2*GTILE) + ((wn*32 + lrow)*TSTRIDE + lcol)*2;
    bbase[s][1] = smem_u32(st + 3*GTILE) + ((wn*32 + lrow)*TSTRIDE + lcol)*2;
  }

#pragma unroll
  for (int mt = 0; mt < 2; mt++)
#pragma unroll
    for (int nt = 0; nt < 4; nt++)
#pragma unroll
      for (int q = 0; q < 4; q++) f.c[mt][nt][q] = 0.f;

  {
    __nv_bfloat16* st = smb;
    cpa_tile128_512(st,           gAh + m0*ldk,    ldk, tid);
    cpa_tile128_512(st + GTILE,   gAl + m0*ldk,    ldk, tid);
    cpa_tile128_512(st + 2*GTILE, gBh + n0blk*ldk, ldk, tid);
    cpa_tile128_512(st + 3*GTILE, gBl + n0blk*ldk, ldk, tid);
    CP_COMMIT();
  }

  for (int kc = 0; kc < KCHUNKS; kc++) {
    if (kc + 1 < KCHUNKS) {
      __nv_bfloat16* st = smb + ((kc+1)&1)*4*GTILE;
      int co = (kc+1)*64;
      cpa_tile128_512(st,           gAh + m0*ldk + co,    ldk, tid);
      cpa_tile128_512(st + GTILE,   gAl + m0*ldk + co,    ldk, tid);
      cpa_tile128_512(st + 2*GTILE, gBh + n0blk*ldk + co, ldk, tid);
      cpa_tile128_512(st + 3*GTILE, gBl + n0blk*ldk + co, ldk, tid);
      CP_COMMIT();
      CP_WAIT(1);
    } else {
      CP_WAIT(0);
    }
    __syncthreads();

    const int s = kc & 1;
#pragma unroll
    for (int ks = 0; ks < 4; ks++) {
      uint32_t ah[2][4], al[2][4];
#pragma unroll
      for (int mt = 0; mt < 2; mt++) {
        uint32_t off = (mt*16*TSTRIDE + ks*16)*2;
        ldsm_x4(abase[s][0] + off, ah[mt][0], ah[mt][1], ah[mt][2], ah[mt][3]);
        ldsm_x4(abase[s][1] + off, al[mt][0], al[mt][1], al[mt][2], al[mt][3]);
      }
      uint32_t bh[4][2], bl[4][2];
#pragma unroll
      for (int np = 0; np < 2; np++) {
        uint32_t off = (np*16*TSTRIDE + ks*16)*2;
        uint32_t r0, r1, r2, r3;
        ldsm_x4(bbase[s][0] + off, r0, r1, r2, r3);
        bh[2*np][0] = r0; bh[2*np+1][0] = r1; bh[2*np][1] = r2; bh[2*np+1][1] = r3;
        ldsm_x4(bbase[s][1] + off, r0, r1, r2, r3);
        bl[2*np][0] = r0; bl[2*np+1][0] = r1; bl[2*np][1] = r2; bl[2*np+1][1] = r3;
      }
#pragma unroll
      for (int mt = 0; mt < 2; mt++)
#pragma unroll
        for (int nt = 0; nt < 4; nt++) {
          mma_bf16(f.c[mt][nt], ah[mt], bh[nt]);
          mma_bf16(f.c[mt][nt], ah[mt], bl[nt]);
          mma_bf16(f.c[mt][nt], al[mt], bh[nt]);
        }
    }
    __syncthreads();
  }
}

// ---------------------------------------------------------------------------
// Projection GEMM (512 threads)
// ---------------------------------------------------------------------------
__global__ __launch_bounds__(512) void proj_mma_kernel(const float* __restrict__ bg)
{
  extern __shared__ __nv_bfloat16 smb[];
  const int tid = threadIdx.x;
  const int c0 = blockIdx.x * 128;
  const int m0 = blockIdx.y * 128;

  FragC f;
  gemm_core<4>(smb, g_xh, g_xl, g_Wch, g_Wcl, m0, c0, 256, tid, f);

  const int lane = tid & 31, wid = tid >> 5;
  const int wm = wid & 3, wn = wid >> 2;
  const int q2 = (lane & 3) * 2, r4 = lane >> 2;
  const int seg = c0 >> 9;
  const int lbase = c0 - seg*512 + wn*32;

#pragma unroll
  for (int mt = 0; mt < 2; mt++) {
#pragma unroll
    for (int h2 = 0; h2 < 2; h2++) {
      const int m = m0 + wm*32 + mt*16 + r4 + h2*8;
      const int bidx = m >> 9, n = m & 511;
      if (seg == 3) {
        float* dst = g_G + m*512 + lbase;
#pragma unroll
        for (int nt = 0; nt < 4; nt++) {
          int cc = nt*8 + q2;
          float2 v;
          v.x = f.c[mt][nt][h2*2+0] + bg[lbase + cc];
          v.y = f.c[mt][nt][h2*2+1] + bg[lbase + cc + 1];
          *(float2*)(dst + cc) = v;
        }
      } else {
        const int hh = lbase >> 6;
        const int dbase = lbase & 63;
        __nv_bfloat16 *bh_, *bl_;
        if (seg == 0)      { bh_ = g_Qh; bl_ = g_Ql; }
        else if (seg == 1) { bh_ = g_Kh; bl_ = g_Kl; }
        else               { bh_ = g_Vh; bl_ = g_Vl; }
        const int off = (((bidx*8 + hh)*512 + n)*64) + dbase;
#pragma unroll
        for (int nt = 0; nt < 4; nt++) {
          int dd = nt*8 + q2;
          __nv_bfloat16 h0, l0, h1, l1;
          split2(f.c[mt][nt][h2*2+0], h0, l0);
          split2(f.c[mt][nt][h2*2+1], h1, l1);
          *(uint32_t*)(bh_ + off + dd) = pack2(h0, h1);
          *(uint32_t*)(bl_ + off + dd) = pack2(l0, l1);
        }
      }
    }
  }
}

// ---------------------------------------------------------------------------
// Output GEMM (512 threads)
// ---------------------------------------------------------------------------
__global__ __launch_bounds__(512) void out_mma_kernel(
    const float* __restrict__ bo, float* __restrict__ Y)
{
  extern __shared__ __nv_bfloat16 smb[];
  const int tid = threadIdx.x;
  const int n0 = blockIdx.x * 128;
  const int m0 = blockIdx.y * 128;

  FragC f;
  gemm_core<8>(smb, g_Eh, g_El, g_Woh, g_Wol, m0, n0, 512, tid, f);

  const int lane = tid & 31, wid = tid >> 5;
  const int wm = wid & 3, wn = wid >> 2;
  const int q2 = (lane & 3) * 2, r4 = lane >> 2;

#pragma unroll
  for (int mt = 0; mt < 2; mt++) {
#pragma unroll
    for (int h2 = 0; h2 < 2; h2++) {
      const int m = m0 + wm*32 + mt*16 + r4 + h2*8;
      float* dst = Y + m*256 + n0 + wn*32;
      const float* bop = bo + n0 + wn*32;
#pragma unroll
      for (int nt = 0; nt < 4; nt++) {
        int cc = nt*8 + q2;
        float2 v;
        v.x = f.c[mt][nt][h2*2+0] + bop[cc];
        v.y = f.c[mt][nt][h2*2+1] + bop[cc + 1];
        *(float2*)(dst + cc) = v;
      }
    }
  }
}

// ---------------------------------------------------------------------------
// Flash attention: block = (b, h, 64 q-rows), 8 warps (4m x 2n).
// Online softmax (exact). Trailing barrier added: V-stage race fix.
// ---------------------------------------------------------------------------
__global__ __launch_bounds__(256, 2) void attn_flash_kernel(
    const float* __restrict__ bias)
{
  extern __shared__ __nv_bfloat16 smb[];
  __nv_bfloat16* Qh = smb;
  __nv_bfloat16* Ql = smb + ATILE;
  __nv_bfloat16* Ph = smb + 2*ATILE;
  __nv_bfloat16* Pl = smb + 3*ATILE;
  float* redM = (float*)(smb + 12*ATILE);
  float* redL = redM + 128;

  const int tid = threadIdx.x;
  const int lane = tid & 31, wid = tid >> 5;
  const int wm = wid & 3, wn = wid >> 2;
  const int lrow = (lane & 7) + ((lane >> 3) & 1) * 8;
  const int lcol = (lane >> 4) * 8;
  const int r4 = lane >> 2, q2 = (lane & 3) * 2;
  const int it0 = blockIdx.x * 64;
  const int h = blockIdx.y, b = blockIdx.z;

  const int bh_off = (b*8 + h) * 512 * 64;
  const __nv_bfloat16* Khs = g_Kh + bh_off;
  const __nv_bfloat16* Kls = g_Kl + bh_off;
  const __nv_bfloat16* Vhs = g_Vh + bh_off;
  const __nv_bfloat16* Vls = g_Vl + bh_off;

  cpa_tile64(Qh, g_Qh + bh_off + it0*64, tid);
  cpa_tile64(Ql, g_Ql + bh_off + it0*64, tid);
  {
    __nv_bfloat16* st = smb + 4*ATILE;
    cpa_tile64(st,           Khs, tid);
    cpa_tile64(st + ATILE,   Kls, tid);
    cpa_tile64(st + 2*ATILE, Vhs, tid);
    cpa_tile64(st + 3*ATILE, Vls, tid);
  }
  CP_COMMIT();

  const uint32_t qh_base = smem_u32(Qh) + ((wm*16 + lrow)*TSTRIDE + lcol)*2;
  const uint32_t ql_base = smem_u32(Ql) + ((wm*16 + lrow)*TSTRIDE + lcol)*2;
  const uint32_t ph_base = smem_u32(Ph) + ((wm*16 + lrow)*TSTRIDE + lcol)*2;
  const uint32_t pl_base = smem_u32(Pl) + ((wm*16 + lrow)*TSTRIDE + lcol)*2;
  uint32_t kb[2][2], vb[2][2];
#pragma unroll
  for (int s = 0; s < 2; s++) {
    __nv_bfloat16* st = smb + (4 + s*4)*ATILE;
    kb[s][0] = smem_u32(st)           + ((wn*32 + lrow)*TSTRIDE + lcol)*2;
    kb[s][1] = smem_u32(st + ATILE)   + ((wn*32 + lrow)*TSTRIDE + lcol)*2;
    vb[s][0] = smem_u32(st + 2*ATILE) + (lrow*TSTRIDE + wn*32 + lcol)*2;
    vb[s][1] = smem_u32(st + 3*ATILE) + (lrow*TSTRIDE + wn*32 + lcol)*2;
  }

  const int row0 = wm*16 + r4;
  const int row1 = row0 + 8;
  const unsigned char* mrow = g_mask + b*512;
  const bool mi0 = mrow[it0 + row0] != 0;
  const bool mi1 = mrow[it0 + row1] != 0;
  const float* brow0 = bias + (h*512 + it0 + row0)*512;
  const float* brow1 = bias + (h*512 + it0 + row1)*512;

  float m0r = -FLT_MAX, m1r = -FLT_MAX, l0r = 0.f, l1r = 0.f;
  float o[4][4];
#pragma unroll
  for (int nf = 0; nf < 4; nf++)
#pragma unroll
    for (int q = 0; q < 4; q++) o[nf][q] = 0.f;

  for (int jt = 0; jt < 8; jt++) {
    if (jt < 7) {
      __nv_bfloat16* st = smb + (4 + ((jt+1)&1)*4)*ATILE;
      const int co = (jt+1)*64*64;
      cpa_tile64(st,           Khs + co, tid);
      cpa_tile64(st + ATILE,   Kls + co, tid);
      cpa_tile64(st + 2*ATILE, Vhs + co, tid);
      cpa_tile64(st + 3*ATILE, Vls + co, tid);
      CP_COMMIT();
      CP_WAIT(1);
    } else {
      CP_WAIT(0);
    }
    __syncthreads();

    const int s = jt & 1;
    float c[4][4];
#pragma unroll
    for (int nf = 0; nf < 4; nf++)
#pragma unroll
      for (int q = 0; q < 4; q++) c[nf][q] = 0.f;

#pragma unroll
    for (int ks = 0; ks < 4; ks++) {
      uint32_t ah[4], al[4];
      ldsm_x4(qh_base + ks*32, ah[0], ah[1], ah[2], ah[3]);
      ldsm_x4(ql_base + ks*32, al[0], al[1], al[2], al[3]);
#pragma unroll
      for (int np = 0; np < 2; np++) {
        uint32_t off = (np*16*TSTRIDE + ks*16)*2;
        uint32_t r0, r1, r2, r3;
        ldsm_x4(kb[s][0] + off, r0, r1, r2, r3);
        uint32_t bh0[2] = {r0, r2}, bh1[2] = {r1, r3};
        ldsm_x4(kb[s][1] + off, r0, r1, r2, r3);
        uint32_t bl0[2] = {r0, r2}, bl1[2] = {r1, r3};
        mma_bf16(c[2*np],   ah, bh0); mma_bf16(c[2*np],   ah, bl0);
        mma_bf16(c[2*np],   al, bh0);
        mma_bf16(c[2*np+1], ah, bh1); mma_bf16(c[2*np+1], ah, bl1);
        mma_bf16(c[2*np+1], al, bh1);
      }
    }

    const int colbase = jt*64 + wn*32;
    float rm0 = -FLT_MAX, rm1 = -FLT_MAX;
#pragma unroll
    for (int nf = 0; nf < 4; nf++) {
      const int col = colbase + nf*8 + q2;
      float2 b0 = *(const float2*)&brow0[col];
      float2 b1 = *(const float2*)&brow1[col];
      bool mjA = mrow[col] != 0, mjB = mrow[col+1] != 0;
      c[nf][0] = (mi0 && mjA) ? c[nf][0]*SCALE_ + b0.x : -FLT_MAX;
      c[nf][1] = (mi0 && mjB) ? c[nf][1]*SCALE_ + b0.y : -FLT_MAX;
      c[nf][2] = (mi1 && mjA) ? c[nf][2]*SCALE_ + b1.x : -FLT_MAX;
      c[nf][3] = (mi1 && mjB) ? c[nf][3]*SCALE_ + b1.y : -FLT_MAX;
      rm0 = fmaxf(rm0, fmaxf(c[nf][0], c[nf][1]));
      rm1 = fmaxf(rm1, fmaxf(c[nf][2], c[nf][3]));
    }
    rm0 = fmaxf(rm0, __shfl_xor_sync(0xffffffffu, rm0, 1));
    rm0 = fmaxf(rm0, __shfl_xor_sync(0xffffffffu, rm0, 2));
    rm1 = fmaxf(rm1, __shfl_xor_sync(0xffffffffu, rm1, 1));
    rm1 = fmaxf(rm1, __shfl_xor_sync(0xffffffffu, rm1, 2));
    if ((lane & 3) == 0) {
      redM[wn*64 + row0] = rm0;
      redM[wn*64 + row1] = rm1;
    }
    __syncthreads();
    const float mc0 = fmaxf(redM[row0], redM[64 + row0]);
    const float mc1 = fmaxf(redM[row1], redM[64 + row1]);
    const float mn0 = fmaxf(m0r, mc0), mn1 = fmaxf(m1r, mc1);
    const float fs0 = __expf(m0r - mn0), fs1 = __expf(m1r - mn1);

    float ls0 = 0.f, ls1 = 0.f;
#pragma unroll
    for (int nf = 0; nf < 4; nf++) {
      c[nf][0] = __expf(c[nf][0] - mn0);
      c[nf][1] = __expf(c[nf][1] - mn0);
      c[nf][2] = __expf(c[nf][2] - mn1);
      c[nf][3] = __expf(c[nf][3] - mn1);
      ls0 += c[nf][0] + c[nf][1];
      ls1 += c[nf][2] + c[nf][3];
    }
    ls0 += __shfl_xor_sync(0xffffffffu, ls0, 1);
    ls0 += __shfl_xor_sync(0xffffffffu, ls0, 2);
    ls1 += __shfl_xor_sync(0xffffffffu, ls1, 1);
    ls1 += __shfl_xor_sync(0xffffffffu, ls1, 2);
    if ((lane & 3) == 0) {
      redL[wn*64 + row0] = ls0;
      redL[wn*64 + row1] = ls1;
    }

#pragma unroll
    for (int nf = 0; nf < 4; nf++) {
      o[nf][0] *= fs0; o[nf][1] *= fs0;
      o[nf][2] *= fs1; o[nf][3] *= fs1;
      const int pcol = wn*32 + nf*8 + q2;
      __nv_bfloat16 h0, lo0, h1, lo1;
      split2(c[nf][0], h0, lo0); split2(c[nf][1], h1, lo1);
      *(uint32_t*)(Ph + row0*TSTRIDE + pcol) = pack2(h0, h1);
      *(uint32_t*)(Pl + row0*TSTRIDE + pcol) = pack2(lo0, lo1);
      split2(c[nf][2], h0, lo0); split2(c[nf][3], h1, lo1);
      *(uint32_t*)(Ph + row1*TSTRIDE + pcol) = pack2(h0, h1);
      *(uint32_t*)(Pl + row1*TSTRIDE + pcol) = pack2(lo0, lo1);
    }
    __syncthreads();
    l0r = l0r*fs0 + redL[row0] + redL[64 + row0];
    l1r = l1r*fs1 + redL[row1] + redL[64 + row1];
    m0r = mn0; m1r = mn1;

#pragma unroll
    for (int ks = 0; ks < 4; ks++) {
      uint32_t ah[4], al[4];
      ldsm_x4(ph_base + ks*32, ah[0], ah[1], ah[2], ah[3]);
      ldsm_x4(pl_base + ks*32, al[0], al[1], al[2], al[3]);
#pragma unroll
      for (int np = 0; np < 2; np++) {
        uint32_t off = (ks*16*TSTRIDE + np*16)*2;
        uint32_t r0, r1, r2, r3;
        ldsm_x4_t(vb[s][0] + off, r0, r1, r2, r3);
        uint32_t bh0[2] = {r0, r1}, bh1[2] = {r2, r3};
        ldsm_x4_t(vb[s][1] + off, r0, r1, r2, r3);
        uint32_t bl0[2] = {r0, r1}, bl1[2] = {r2, r3};
        mma_bf16(o[2*np],   ah, bh0); mma_bf16(o[2*np],   ah, bl0);
        mma_bf16(o[2*np],   al, bh0);
        mma_bf16(o[2*np+1], ah, bh1); mma_bf16(o[2*np+1], ah, bl1);
        mma_bf16(o[2*np+1], al, bh1);
      }
    }
    // RACE FIX: all warps must finish reading this V stage before any warp
    // issues next iteration's cp.async into the same buffer.
    __syncthreads();
  }

  const float inv0 = 1.0f / l0r;
  const float inv1 = 1.0f / l1r;
#pragma unroll
  for (int nf = 0; nf < 4; nf++) {
    const int d = wn*32 + nf*8 + q2;
#pragma unroll
    for (int h2 = 0; h2 < 2; h2++) {
      const int row = (h2 == 0) ? row0 : row1;
      const float inv = (h2 == 0) ? inv0 : inv1;
      const int idx = (b*512 + it0 + row)*512 + h*64 + d;
      float2 gv = *(const float2*)(g_G + idx);
      float e0 = o[nf][h2*2+0] * inv * gv.x;
      float e1 = o[nf][h2*2+1] * inv * gv.y;
      __nv_bfloat16 eh0, el0, eh1, el1;
      split2(e0, eh0, el0); split2(e1, eh1, el1);
      *(uint32_t*)(g_Eh + idx) = pack2(eh0, eh1);
      *(uint32_t*)(g_El + idx) = pack2(el0, el1);
    }
  }
}

// ---------------------------------------------------------------------------
extern "C" void kernel_launch(void* const* d_in, const int* in_sizes, int n_in,
                              void* d_out, int out_size)
{
  const float* x   = (const float*)d_in[0];
  const void*  mask = d_in[1];
  const float* bias = (const float*)d_in[2];
  const float* Wq  = (const float*)d_in[3];
  const float* Wkv = (const float*)d_in[4];
  const float* Wo  = (const float*)d_in[5];
  const float* bo  = (const float*)d_in[6];
  const float* Wg  = (const float*)d_in[7];
  const float* bg  = (const float*)d_in[8];
  float* Y = (float*)d_out;

  const int SMEM_ATTN = 12*ATILE*2 + 256*4;
  const int SMEM_MMA  = 8 * GTILE * 2;
  cudaFuncSetAttribute(attn_flash_kernel, cudaFuncAttributeMaxDynamicSharedMemorySize,
                       SMEM_ATTN);
  cudaFuncSetAttribute(proj_mma_kernel, cudaFuncAttributeMaxDynamicSharedMemorySize,
                       SMEM_MMA);
  cudaFuncSetAttribute(out_mma_kernel, cudaFuncAttributeMaxDynamicSharedMemorySize,
                       SMEM_MMA);

  detect_mask_kernel<<<1, 256>>>((const unsigned int*)mask);
  convert_mask_kernel<<<128, 256>>>(mask);
  split_x_kernel<<<8192, 256>>>(x);
  split_W_kernel<<<2048, 256>>>(Wq, Wkv, Wg);
  split_Wo_kernel<<<512, 256>>>(Wo);
  proj_mma_kernel<<<dim3(16, 256), 512, SMEM_MMA>>>(bg);
  attn_flash_kernel<<<dim3(8, 8, 64), 256, SMEM_ATTN>>>(bias);
  out_mma_kernel<<<dim3(2, 256), 512, SMEM_MMA>>>(bo, Y);
}